// round 10
// baseline (speedup 1.0000x reference)
#include <cuda_runtime.h>
#include <mma.h>
#include <math.h>
#include <stdint.h>
#include <cuda_fp16.h>

using namespace nvcuda;

#define NN      50000
#define NP      50048            // NN padded to multiple of 128
#define EE      800000
#define NFEAT   512
#define NHID    256
#define NCODE   64
#define NCLASS  40

// ---------------- device scratch (static, allocation-free) ----------------
__device__ __align__(16) __half g_support1h[(size_t)NP * NHID]; // x @ W1 (fp16)
__device__ __align__(16) __half g_h1h[(size_t)NP * NHID];       // relu(spmm + b1) fp16
__device__ float g_tmp     [(size_t)NP * 128];    // h1 @ [Wmu|Wlv] fp32
__device__ __align__(16) __half g_x1h[(size_t)NP * NHID];       // z @ Wdec (fp16)
__device__ float g_support2[(size_t)NP * 64];     // concat @ W2 (padded cols)
__device__ int   g_cnt   [NN];
__device__ int   g_rowptr[NN + 1];
__device__ int   g_cursor[NN];
__device__ int   g_esrc[EE];
__device__ float g_ew  [EE];

__device__ __forceinline__ unsigned h2u(__half2 h) {
    return *(unsigned*)&h;
}

// convert 16 fp32 (as 4 float4) -> 2 uint4 of halves
__device__ __forceinline__ void cvt16(uint4& u0, uint4& u1,
                                      float4 a0, float4 a1, float4 a2, float4 a3) {
    u0 = make_uint4(h2u(__floats2half2_rn(a0.x, a0.y)), h2u(__floats2half2_rn(a0.z, a0.w)),
                    h2u(__floats2half2_rn(a1.x, a1.y)), h2u(__floats2half2_rn(a1.z, a1.w)));
    u1 = make_uint4(h2u(__floats2half2_rn(a2.x, a2.y)), h2u(__floats2half2_rn(a2.z, a2.w)),
                    h2u(__floats2half2_rn(a3.x, a3.y)), h2u(__floats2half2_rn(a3.z, a3.w)));
}

// ---------------- CSR build ----------------
__global__ void hist_kernel(const int* __restrict__ dst) {
    int e = blockIdx.x * blockDim.x + threadIdx.x;
    if (e < EE) atomicAdd(&g_cnt[dst[e]], 1);
}

__global__ __launch_bounds__(1024) void scan_kernel() {
    __shared__ int sums[1024];
    const int T = 1024;
    const int IT = (NN + T - 1) / T;
    int t = threadIdx.x;
    int base = t * IT;
    int s = 0;
    for (int i = 0; i < IT; i++) {
        int idx = base + i;
        if (idx < NN) s += g_cnt[idx];
    }
    sums[t] = s;
    __syncthreads();
    for (int off = 1; off < T; off <<= 1) {
        int v = (t >= off) ? sums[t - off] : 0;
        __syncthreads();
        sums[t] += v;
        __syncthreads();
    }
    int run = sums[t] - s;
    for (int i = 0; i < IT; i++) {
        int idx = base + i;
        if (idx < NN) {
            g_rowptr[idx] = run;
            g_cursor[idx] = run;
            run += g_cnt[idx];
        }
    }
    if (t == T - 1) g_rowptr[NN] = sums[T - 1];
}

__global__ void scatter_kernel(const int* __restrict__ src,
                               const int* __restrict__ dst,
                               const float* __restrict__ w) {
    int e = blockIdx.x * blockDim.x + threadIdx.x;
    if (e < EE) {
        int d = dst[e];
        int p = atomicAdd(&g_cursor[d], 1);
        g_esrc[p] = src[e];
        g_ew[p]   = w[e];
    }
}

// =========================================================================
// GEMM1 (fp16 HMMA): g_support1h = fp16(x @ W1)
// M=NP, K=512, N=256. BM=128, BN=256 (full N), BK=32.
// 8 warps (2x4), warp tile 64x64 (4x4 fragments) — minimizes LDSM/MMA.
// =========================================================================
__global__ __launch_bounds__(256) void gemm1_tc(const float* __restrict__ A,
                                                const float* __restrict__ B) {
    __shared__ __half As[128][40];
    __shared__ __half Bs[32][264];
    const int t   = threadIdx.x;
    const int wid = t >> 5;
    const int wr  = wid >> 2;     // 0..1  (64-row band)
    const int wc  = wid & 3;      // 0..3  (64-col band)
    const int row0 = blockIdx.x * 128;

    wmma::fragment<wmma::accumulator, 16, 16, 16, float> acc[4][4];
#pragma unroll
    for (int i = 0; i < 4; i++)
#pragma unroll
        for (int j = 0; j < 4; j++) wmma::fill_fragment(acc[i][j], 0.0f);

    const int arow = t >> 1;          // 0..127
    const int ac16 = (t & 1) * 16;    // 0/16
    const int brow = t >> 3;          // 0..31
    const int bc32 = (t & 7) * 32;    // 0..224
    int garow = row0 + arow; if (garow >= NN) garow = NN - 1;
    const float* Ap = A + (size_t)garow * NFEAT;

    for (int k0 = 0; k0 < NFEAT; k0 += 32) {
        {
            const float* ap = Ap + k0 + ac16;
            float4 a0 = *(const float4*)(ap);
            float4 a1 = *(const float4*)(ap + 4);
            float4 a2 = *(const float4*)(ap + 8);
            float4 a3 = *(const float4*)(ap + 12);
            uint4 u0, u1; cvt16(u0, u1, a0, a1, a2, a3);
            *(uint4*)&As[arow][ac16]     = u0;
            *(uint4*)&As[arow][ac16 + 8] = u1;

            const float* bp = B + (size_t)(k0 + brow) * NHID + bc32;
            float4 b0 = *(const float4*)(bp);
            float4 b1 = *(const float4*)(bp + 4);
            float4 b2 = *(const float4*)(bp + 8);
            float4 b3 = *(const float4*)(bp + 12);
            uint4 v0, v1; cvt16(v0, v1, b0, b1, b2, b3);
            *(uint4*)&Bs[brow][bc32]     = v0;
            *(uint4*)&Bs[brow][bc32 + 8] = v1;
            float4 c0 = *(const float4*)(bp + 16);
            float4 c1 = *(const float4*)(bp + 20);
            float4 c2 = *(const float4*)(bp + 24);
            float4 c3 = *(const float4*)(bp + 28);
            uint4 w0, w1; cvt16(w0, w1, c0, c1, c2, c3);
            *(uint4*)&Bs[brow][bc32 + 16] = w0;
            *(uint4*)&Bs[brow][bc32 + 24] = w1;
        }
        __syncthreads();
#pragma unroll
        for (int kk = 0; kk < 32; kk += 16) {
            wmma::fragment<wmma::matrix_a, 16, 16, 16, __half, wmma::row_major> af[4];
            wmma::fragment<wmma::matrix_b, 16, 16, 16, __half, wmma::row_major> bf[4];
#pragma unroll
            for (int i = 0; i < 4; i++)
                wmma::load_matrix_sync(af[i], &As[wr * 64 + i * 16][kk], 40);
#pragma unroll
            for (int j = 0; j < 4; j++)
                wmma::load_matrix_sync(bf[j], &Bs[kk][wc * 64 + j * 16], 264);
#pragma unroll
            for (int i = 0; i < 4; i++)
#pragma unroll
                for (int j = 0; j < 4; j++)
                    wmma::mma_sync(acc[i][j], af[i], bf[j], acc[i][j]);
        }
        __syncthreads();
    }

    // fp16 epilogue: stage through smem (reuse As as float buffer)
    float* stage = (float*)&As[0][0] + wid * 320;   // 16x20 floats per warp
    const int L = t & 31;
    const int rr = L >> 1;
    const int cc = (L & 1) * 8;
#pragma unroll
    for (int i = 0; i < 4; i++)
#pragma unroll
        for (int j = 0; j < 4; j++) {
            wmma::store_matrix_sync(stage, acc[i][j], 20, wmma::mem_row_major);
            __syncwarp();
            const float* sp = stage + rr * 20 + cc;
            __half2 h0 = __floats2half2_rn(sp[0], sp[1]);
            __half2 h1 = __floats2half2_rn(sp[2], sp[3]);
            __half2 h2 = __floats2half2_rn(sp[4], sp[5]);
            __half2 h3 = __floats2half2_rn(sp[6], sp[7]);
            int gr = row0 + wr * 64 + i * 16 + rr;
            int gc = wc * 64 + j * 16 + cc;
            *(uint4*)(g_support1h + (size_t)gr * NHID + gc) =
                make_uint4(h2u(h0), h2u(h1), h2u(h2), h2u(h3));
            __syncwarp();
        }
}

// =========================================================================
// zgemm (fp16 HMMA): g_tmp = h1 @ [Wmu | Wlv]   M=NP, K=256, N=128.
// =========================================================================
__global__ __launch_bounds__(256) void zgemm_tc(const float* __restrict__ Wmu,
                                                const float* __restrict__ Wlv) {
    __shared__ __half As[128][40];
    __shared__ __half Bs[32][136];
    const int t   = threadIdx.x;
    const int wid = t >> 5;
    const int wr  = wid >> 2;
    const int wc  = wid & 3;
    const int row0 = blockIdx.x * 128;

    wmma::fragment<wmma::accumulator, 16, 16, 16, float> acc[4][2];
#pragma unroll
    for (int i = 0; i < 4; i++)
#pragma unroll
        for (int j = 0; j < 2; j++) wmma::fill_fragment(acc[i][j], 0.0f);

    const int arow = t >> 1;
    const int ac16 = (t & 1) * 16;
    const int brow = t >> 3;
    const int bc16 = (t & 7) * 16;
    int garow = row0 + arow; if (garow >= NN) garow = NN - 1;
    const __half* Ap = g_h1h + (size_t)garow * NHID;
    const float* Bbase = (bc16 < 64) ? Wmu : Wlv;
    const int bco = (bc16 < 64) ? bc16 : (bc16 - 64);

    for (int k0 = 0; k0 < NHID; k0 += 32) {
        {
            const __half* ap = Ap + k0 + ac16;
            *(uint4*)&As[arow][ac16]     = *(const uint4*)(ap);
            *(uint4*)&As[arow][ac16 + 8] = *(const uint4*)(ap + 8);
            const float* bp = Bbase + (size_t)(k0 + brow) * NCODE + bco;
            float4 b0 = *(const float4*)(bp);
            float4 b1 = *(const float4*)(bp + 4);
            float4 b2 = *(const float4*)(bp + 8);
            float4 b3 = *(const float4*)(bp + 12);
            uint4 v0, v1; cvt16(v0, v1, b0, b1, b2, b3);
            *(uint4*)&Bs[brow][bc16]     = v0;
            *(uint4*)&Bs[brow][bc16 + 8] = v1;
        }
        __syncthreads();
#pragma unroll
        for (int kk = 0; kk < 32; kk += 16) {
            wmma::fragment<wmma::matrix_a, 16, 16, 16, __half, wmma::row_major> af[4];
            wmma::fragment<wmma::matrix_b, 16, 16, 16, __half, wmma::row_major> bf[2];
#pragma unroll
            for (int i = 0; i < 4; i++)
                wmma::load_matrix_sync(af[i], &As[wr * 64 + i * 16][kk], 40);
#pragma unroll
            for (int j = 0; j < 2; j++)
                wmma::load_matrix_sync(bf[j], &Bs[kk][wc * 32 + j * 16], 136);
#pragma unroll
            for (int i = 0; i < 4; i++)
#pragma unroll
                for (int j = 0; j < 2; j++)
                    wmma::mma_sync(acc[i][j], af[i], bf[j], acc[i][j]);
        }
        __syncthreads();
    }
#pragma unroll
    for (int i = 0; i < 4; i++)
#pragma unroll
        for (int j = 0; j < 2; j++) {
            int r = row0 + wr * 64 + i * 16;
            int c = wc * 32 + j * 16;
            wmma::store_matrix_sync(g_tmp + (size_t)r * 128 + c, acc[i][j],
                                    128, wmma::mem_row_major);
        }
}

// =========================================================================
// dec gemm (fp16 HMMA): g_x1h = fp16(z @ Wdec), z on the fly:
//   z = (mu + bmu) + eps * exp(lv + blv)
// M=NP, K=64, N=256. grid (2, NP/128)
// =========================================================================
__global__ __launch_bounds__(256) void dec_tc(const float* __restrict__ Wdec,
                                              const float* __restrict__ bmu,
                                              const float* __restrict__ blv,
                                              const float* __restrict__ eps) {
    __shared__ __half As[128][40];
    __shared__ __half Bs[32][136];
    const int t   = threadIdx.x;
    const int wid = t >> 5;
    const int wr  = wid >> 2;
    const int wc  = wid & 3;
    const int row0 = blockIdx.y * 128;
    const int col0 = blockIdx.x * 128;

    wmma::fragment<wmma::accumulator, 16, 16, 16, float> acc[4][2];
#pragma unroll
    for (int i = 0; i < 4; i++)
#pragma unroll
        for (int j = 0; j < 2; j++) wmma::fill_fragment(acc[i][j], 0.0f);

    const int arow = t >> 1;
    const int ac16 = (t & 1) * 16;
    const int brow = t >> 3;
    const int bc16 = (t & 7) * 16;
    int garow = row0 + arow; if (garow >= NN) garow = NN - 1;
    const float* Mp = g_tmp + (size_t)garow * 128;
    const float* Ep = eps + (size_t)garow * NCODE;

    for (int k0 = 0; k0 < NCODE; k0 += 32) {
        {
            float z[16];
#pragma unroll
            for (int h = 0; h < 4; h++) {
                int c = k0 + ac16 + h * 4;
                float4 m  = *(const float4*)(Mp + c);
                float4 l  = *(const float4*)(Mp + 64 + c);
                float4 e  = *(const float4*)(Ep + c);
                float4 bm = *(const float4*)(bmu + c);
                float4 bl = *(const float4*)(blv + c);
                z[h * 4 + 0] = (m.x + bm.x) + e.x * expf(l.x + bl.x);
                z[h * 4 + 1] = (m.y + bm.y) + e.y * expf(l.y + bl.y);
                z[h * 4 + 2] = (m.z + bm.z) + e.z * expf(l.z + bl.z);
                z[h * 4 + 3] = (m.w + bm.w) + e.w * expf(l.w + bl.w);
            }
            uint4 u0, u1;
            cvt16(u0, u1,
                  make_float4(z[0], z[1], z[2], z[3]),
                  make_float4(z[4], z[5], z[6], z[7]),
                  make_float4(z[8], z[9], z[10], z[11]),
                  make_float4(z[12], z[13], z[14], z[15]));
            *(uint4*)&As[arow][ac16]     = u0;
            *(uint4*)&As[arow][ac16 + 8] = u1;
            const float* bp = Wdec + (size_t)(k0 + brow) * NHID + col0 + bc16;
            float4 b0 = *(const float4*)(bp);
            float4 b1 = *(const float4*)(bp + 4);
            float4 b2 = *(const float4*)(bp + 8);
            float4 b3 = *(const float4*)(bp + 12);
            uint4 v0, v1; cvt16(v0, v1, b0, b1, b2, b3);
            *(uint4*)&Bs[brow][bc16]     = v0;
            *(uint4*)&Bs[brow][bc16 + 8] = v1;
        }
        __syncthreads();
#pragma unroll
        for (int kk = 0; kk < 32; kk += 16) {
            wmma::fragment<wmma::matrix_a, 16, 16, 16, __half, wmma::row_major> af[4];
            wmma::fragment<wmma::matrix_b, 16, 16, 16, __half, wmma::row_major> bf[2];
#pragma unroll
            for (int i = 0; i < 4; i++)
                wmma::load_matrix_sync(af[i], &As[wr * 64 + i * 16][kk], 40);
#pragma unroll
            for (int j = 0; j < 2; j++)
                wmma::load_matrix_sync(bf[j], &Bs[kk][wc * 32 + j * 16], 136);
#pragma unroll
            for (int i = 0; i < 4; i++)
#pragma unroll
                for (int j = 0; j < 2; j++)
                    wmma::mma_sync(acc[i][j], af[i], bf[j], acc[i][j]);
        }
        __syncthreads();
    }

    // fp16 epilogue
    float* stage = (float*)&As[0][0] + wid * 320;
    const int L = t & 31;
    const int rr = L >> 1;
    const int cc = (L & 1) * 8;
#pragma unroll
    for (int i = 0; i < 4; i++)
#pragma unroll
        for (int j = 0; j < 2; j++) {
            wmma::store_matrix_sync(stage, acc[i][j], 20, wmma::mem_row_major);
            __syncwarp();
            const float* sp = stage + rr * 20 + cc;
            __half2 h0 = __floats2half2_rn(sp[0], sp[1]);
            __half2 h1 = __floats2half2_rn(sp[2], sp[3]);
            __half2 h2 = __floats2half2_rn(sp[4], sp[5]);
            __half2 h3 = __floats2half2_rn(sp[6], sp[7]);
            int gr = row0 + wr * 64 + i * 16 + rr;
            int gc = col0 + wc * 32 + j * 16 + cc;
            *(uint4*)(g_x1h + (size_t)gr * NHID + gc) =
                make_uint4(h2u(h0), h2u(h1), h2u(h2), h2u(h3));
            __syncwarp();
        }
}

// =========================================================================
// out gemm (fp16 HMMA): g_support2 = [relu(x1+bdec) ; h1] @ W2
// M=NP, K=512, N=40 (padded 64). 8 warps (4x2), warp 32x32. BK=32.
// =========================================================================
__global__ __launch_bounds__(256) void out_tc(const float* __restrict__ W2,
                                              const float* __restrict__ bdec) {
    __shared__ __half As[128][40];
    __shared__ __half Bs[32][72];
    const int t   = threadIdx.x;
    const int wid = t >> 5;
    const int wr  = wid >> 1;     // 0..3
    const int wc  = wid & 1;      // 0..1
    const int row0 = blockIdx.x * 128;

    wmma::fragment<wmma::accumulator, 16, 16, 16, float> acc[2][2];
#pragma unroll
    for (int i = 0; i < 2; i++)
#pragma unroll
        for (int j = 0; j < 2; j++) wmma::fill_fragment(acc[i][j], 0.0f);

    const int arow = t >> 1;
    const int ac16 = (t & 1) * 16;
    const int brow = t >> 3;          // 0..31
    const int bc8  = (t & 7) * 8;     // 0..56
    int garow = row0 + arow; if (garow >= NN) garow = NN - 1;
    const __half* Ap1 = g_x1h + (size_t)garow * NHID;
    const __half* Ap2 = g_h1h + (size_t)garow * NHID;

    for (int k0 = 0; k0 < 2 * NHID; k0 += 32) {
        {
            if (k0 < NHID) {
                const __half* ap = Ap1 + k0 + ac16;
                uint4 u0 = *(const uint4*)(ap);
                uint4 u1 = *(const uint4*)(ap + 8);
                __half2* hp0 = (__half2*)&u0;
                __half2* hp1 = (__half2*)&u1;
                float v[16];
#pragma unroll
                for (int q = 0; q < 4; q++) {
                    float2 f = __half22float2(hp0[q]);
                    v[2 * q] = f.x; v[2 * q + 1] = f.y;
                    float2 g = __half22float2(hp1[q]);
                    v[8 + 2 * q] = g.x; v[8 + 2 * q + 1] = g.y;
                }
                const float* bd = bdec + k0 + ac16;
#pragma unroll
                for (int q = 0; q < 16; q++)
                    v[q] = fmaxf(v[q] + bd[q], 0.0f);
                uint4 w0, w1;
                cvt16(w0, w1,
                      make_float4(v[0], v[1], v[2], v[3]),
                      make_float4(v[4], v[5], v[6], v[7]),
                      make_float4(v[8], v[9], v[10], v[11]),
                      make_float4(v[12], v[13], v[14], v[15]));
                *(uint4*)&As[arow][ac16]     = w0;
                *(uint4*)&As[arow][ac16 + 8] = w1;
            } else {
                const __half* ap = Ap2 + (k0 - NHID) + ac16;
                *(uint4*)&As[arow][ac16]     = *(const uint4*)(ap);
                *(uint4*)&As[arow][ac16 + 8] = *(const uint4*)(ap + 8);
            }
            float4 b0 = make_float4(0.f, 0.f, 0.f, 0.f);
            float4 b1 = make_float4(0.f, 0.f, 0.f, 0.f);
            if (bc8 < NCLASS) {
                const float* bp = W2 + (size_t)(k0 + brow) * NCLASS + bc8;
                b0 = *(const float4*)(bp);
                b1 = *(const float4*)(bp + 4);
            }
            uint4 v0 = make_uint4(h2u(__floats2half2_rn(b0.x, b0.y)),
                                  h2u(__floats2half2_rn(b0.z, b0.w)),
                                  h2u(__floats2half2_rn(b1.x, b1.y)),
                                  h2u(__floats2half2_rn(b1.z, b1.w)));
            *(uint4*)&Bs[brow][bc8] = v0;
        }
        __syncthreads();
#pragma unroll
        for (int kk = 0; kk < 32; kk += 16) {
            wmma::fragment<wmma::matrix_a, 16, 16, 16, __half, wmma::row_major> af[2];
            wmma::fragment<wmma::matrix_b, 16, 16, 16, __half, wmma::row_major> bf[2];
#pragma unroll
            for (int i = 0; i < 2; i++)
                wmma::load_matrix_sync(af[i], &As[wr * 32 + i * 16][kk], 40);
#pragma unroll
            for (int j = 0; j < 2; j++)
                wmma::load_matrix_sync(bf[j], &Bs[kk][wc * 32 + j * 16], 72);
#pragma unroll
            for (int i = 0; i < 2; i++)
#pragma unroll
                for (int j = 0; j < 2; j++)
                    wmma::mma_sync(acc[i][j], af[i], bf[j], acc[i][j]);
        }
        __syncthreads();
    }
#pragma unroll
    for (int i = 0; i < 2; i++)
#pragma unroll
        for (int j = 0; j < 2; j++) {
            int r = row0 + wr * 32 + i * 16;
            int c = wc * 32 + j * 16;
            wmma::store_matrix_sync(g_support2 + (size_t)r * 64 + c, acc[i][j],
                                    64, wmma::mem_row_major);
        }
}

// ---------------- spmm1 + bias + relu (fp16 gather -> fp16 h1) -----------
__global__ void spmm_relu_kernel(const float* __restrict__ b1) {
    int warp = (blockIdx.x * blockDim.x + threadIdx.x) >> 5;
    int lane = threadIdx.x & 31;
    if (warp >= NN) return;
    int beg = g_rowptr[warp];
    int end = g_rowptr[warp + 1];
    float acc[8] = {0, 0, 0, 0, 0, 0, 0, 0};
    const int co = lane * 8;
    int e = beg;
    for (; e + 4 <= end; e += 4) {
        int   s0 = g_esrc[e],   s1 = g_esrc[e + 1], s2 = g_esrc[e + 2], s3 = g_esrc[e + 3];
        float w0 = g_ew[e],     w1 = g_ew[e + 1],   w2 = g_ew[e + 2],   w3 = g_ew[e + 3];
        uint4 u0 = *(const uint4*)(g_support1h + (size_t)s0 * NHID + co);
        uint4 u1 = *(const uint4*)(g_support1h + (size_t)s1 * NHID + co);
        uint4 u2 = *(const uint4*)(g_support1h + (size_t)s2 * NHID + co);
        uint4 u3 = *(const uint4*)(g_support1h + (size_t)s3 * NHID + co);
        __half2* h0 = (__half2*)&u0;
        __half2* h1 = (__half2*)&u1;
        __half2* h2 = (__half2*)&u2;
        __half2* h3 = (__half2*)&u3;
#pragma unroll
        for (int q = 0; q < 4; q++) {
            float2 f0 = __half22float2(h0[q]);
            float2 f1 = __half22float2(h1[q]);
            float2 f2 = __half22float2(h2[q]);
            float2 f3 = __half22float2(h3[q]);
            acc[2 * q]     += w0 * f0.x + w1 * f1.x + w2 * f2.x + w3 * f3.x;
            acc[2 * q + 1] += w0 * f0.y + w1 * f1.y + w2 * f2.y + w3 * f3.y;
        }
    }
    for (; e < end; e++) {
        int s = g_esrc[e];
        float w = g_ew[e];
        uint4 u = *(const uint4*)(g_support1h + (size_t)s * NHID + co);
        __half2* h = (__half2*)&u;
#pragma unroll
        for (int q = 0; q < 4; q++) {
            float2 f = __half22float2(h[q]);
            acc[2 * q]     += w * f.x;
            acc[2 * q + 1] += w * f.y;
        }
    }
    float4 bb0 = *(const float4*)(b1 + co);
    float4 bb1 = *(const float4*)(b1 + co + 4);
    float o[8];
    o[0] = fmaxf(acc[0] + bb0.x, 0.f); o[1] = fmaxf(acc[1] + bb0.y, 0.f);
    o[2] = fmaxf(acc[2] + bb0.z, 0.f); o[3] = fmaxf(acc[3] + bb0.w, 0.f);
    o[4] = fmaxf(acc[4] + bb1.x, 0.f); o[5] = fmaxf(acc[5] + bb1.y, 0.f);
    o[6] = fmaxf(acc[6] + bb1.z, 0.f); o[7] = fmaxf(acc[7] + bb1.w, 0.f);
    uint4 u = make_uint4(h2u(__floats2half2_rn(o[0], o[1])),
                         h2u(__floats2half2_rn(o[2], o[3])),
                         h2u(__floats2half2_rn(o[4], o[5])),
                         h2u(__floats2half2_rn(o[6], o[7])));
    *(uint4*)(g_h1h + (size_t)warp * NHID + co) = u;
}

// ---------------- spmm2 + b2 + log_softmax -> out ----------------
__global__ void spmm_softmax_kernel(const float* __restrict__ b2,
                                    float* __restrict__ out) {
    int warp = (blockIdx.x * blockDim.x + threadIdx.x) >> 5;
    int lane = threadIdx.x & 31;
    if (warp >= NN) return;
    int beg = g_rowptr[warp];
    int end = g_rowptr[warp + 1];
    bool active = lane < 10;
    float4 acc = make_float4(0, 0, 0, 0);
    const float4* S = (const float4*)g_support2;   // stride 16 float4 / row
    for (int e = beg; e < end; e++) {
        int s = g_esrc[e];
        float w = g_ew[e];
        if (active) {
            float4 v = __ldg(S + (size_t)s * 16 + lane);
            acc.x += w * v.x; acc.y += w * v.y; acc.z += w * v.z; acc.w += w * v.w;
        }
    }
    float4 v = make_float4(-INFINITY, -INFINITY, -INFINITY, -INFINITY);
    if (active) {
        float4 b = ((const float4*)b2)[lane];
        v.x = acc.x + b.x; v.y = acc.y + b.y; v.z = acc.z + b.z; v.w = acc.w + b.w;
    }
    float m = fmaxf(fmaxf(v.x, v.y), fmaxf(v.z, v.w));
#pragma unroll
    for (int off = 16; off > 0; off >>= 1)
        m = fmaxf(m, __shfl_xor_sync(0xFFFFFFFFu, m, off));
    float s = active ? (expf(v.x - m) + expf(v.y - m) + expf(v.z - m) + expf(v.w - m)) : 0.0f;
#pragma unroll
    for (int off = 16; off > 0; off >>= 1)
        s += __shfl_xor_sync(0xFFFFFFFFu, s, off);
    float lse = m + logf(s);
    if (active) {
        float4 o;
        o.x = v.x - lse; o.y = v.y - lse; o.z = v.z - lse; o.w = v.w - lse;
        ((float4*)out)[(size_t)warp * 10 + lane] = o;
    }
}

// ---------------- launch ----------------
extern "C" void kernel_launch(void* const* d_in, const int* in_sizes, int n_in,
                              void* d_out, int out_size) {
    const float* x        = (const float*)d_in[0];
    const int*   edge_src = (const int*)  d_in[1];
    const int*   edge_dst = (const int*)  d_in[2];
    const float* edge_w   = (const float*)d_in[3];
    const float* eps      = (const float*)d_in[4];
    const float* W1       = (const float*)d_in[5];
    const float* b1       = (const float*)d_in[6];
    const float* W_mu     = (const float*)d_in[7];
    const float* b_mu     = (const float*)d_in[8];
    const float* W_lv     = (const float*)d_in[9];
    const float* b_lv     = (const float*)d_in[10];
    const float* W_dec    = (const float*)d_in[11];
    const float* b_dec    = (const float*)d_in[12];
    const float* W2       = (const float*)d_in[13];
    const float* b2       = (const float*)d_in[14];
    float* out = (float*)d_out;

    // zero counts via async memset
    void* cnt_ptr = nullptr;
    cudaGetSymbolAddress(&cnt_ptr, g_cnt);
    cudaMemsetAsync(cnt_ptr, 0, NN * sizeof(int));

    // kernel index:       0            1           2              3 (ncu window)
    hist_kernel<<<(EE + 255) / 256, 256>>>(edge_dst);
    scan_kernel<<<1, 1024>>>();
    scatter_kernel<<<(EE + 255) / 256, 256>>>(edge_src, edge_dst, edge_w);
    gemm1_tc<<<NP / 128, 256>>>(x, W1);

    // h1(fp16) = relu(spmm + b1)
    spmm_relu_kernel<<<(NN * 32 + 255) / 256, 256>>>(b1);

    // tmp = h1 @ [Wmu|Wlv]
    zgemm_tc<<<NP / 128, 256>>>(W_mu, W_lv);

    // x1(fp16) = z @ Wdec, z on the fly
    dec_tc<<<dim3(NHID / 128, NP / 128), 256>>>(W_dec, b_mu, b_lv, eps);

    // support2 = [relu(x1+bdec); h1] @ W2
    out_tc<<<NP / 128, 256>>>(W2, b_dec);

    // out = log_softmax(spmm + b2)
    spmm_softmax_kernel<<<(NN * 32 + 255) / 256, 256>>>(b2, out);
}

// round 11
// speedup vs baseline: 1.2294x; 1.2294x over previous
#include <cuda_runtime.h>
#include <mma.h>
#include <math.h>
#include <stdint.h>
#include <cuda_fp16.h>

using namespace nvcuda;

#define NN      50000
#define NP      50048            // NN padded to multiple of 128
#define EE      800000
#define NFEAT   512
#define NHID    256
#define NCODE   64
#define NCLASS  40

// ---------------- device scratch (static, allocation-free) ----------------
__device__ __align__(16) __half g_xh  [(size_t)NN * NFEAT];     // fp16(x)
__device__ __align__(16) __half g_w1h [NFEAT * NHID];           // fp16(W1)
__device__ __align__(16) __half g_wmlh[NHID * 128];             // fp16([Wmu|Wlv])
__device__ __align__(16) __half g_wdech[NCODE * NHID];          // fp16(Wdec)
__device__ __align__(16) __half g_w2h [2 * NHID * 64];          // fp16(W2) padded cols
__device__ __align__(16) __half g_support1h[(size_t)NP * NHID]; // x @ W1 (fp16)
__device__ __align__(16) __half g_h1h[(size_t)NP * NHID];       // relu(spmm + b1) fp16
__device__ float g_tmp     [(size_t)NP * 128];    // h1 @ [Wmu|Wlv] fp32
__device__ __align__(16) __half g_x1h[(size_t)NP * NHID];       // relu(z @ Wdec + bdec) fp16
__device__ float g_support2[(size_t)NP * 64];     // concat @ W2 (padded cols)
__device__ int   g_cnt   [NN];
__device__ int   g_rowptr[NN + 1];
__device__ int   g_cursor[NN];
__device__ int   g_esrc[EE];
__device__ float g_ew  [EE];

__device__ __forceinline__ unsigned h2u(__half2 h) {
    return *(unsigned*)&h;
}

__device__ __forceinline__ void cp_async16(void* smem, const void* gmem) {
    unsigned int s = (unsigned int)__cvta_generic_to_shared(smem);
    asm volatile("cp.async.cg.shared.global [%0], [%1], 16;" :: "r"(s), "l"(gmem));
}
__device__ __forceinline__ void cp_commit() {
    asm volatile("cp.async.commit_group;");
}
__device__ __forceinline__ void cp_wait1() {
    asm volatile("cp.async.wait_group 1;");
}
__device__ __forceinline__ void cp_wait0() {
    asm volatile("cp.async.wait_group 0;");
}

// ---------------- fp16 conversion kernels ----------------
__global__ void cvt_w_kernel(const float* __restrict__ W1,
                             const float* __restrict__ Wmu,
                             const float* __restrict__ Wlv,
                             const float* __restrict__ Wdec,
                             const float* __restrict__ W2) {
    int i = blockIdx.x * blockDim.x + threadIdx.x;
    if (i < NFEAT * NHID) g_w1h[i] = __float2half_rn(W1[i]);
    if (i < NHID * 128) {
        int k = i >> 7, j = i & 127;
        float v = (j < 64) ? Wmu[k * NCODE + j] : Wlv[k * NCODE + (j - 64)];
        g_wmlh[i] = __float2half_rn(v);
    }
    if (i < NCODE * NHID) g_wdech[i] = __float2half_rn(Wdec[i]);
    if (i < 2 * NHID * 64) {
        int k = i >> 6, j = i & 63;
        g_w2h[i] = __float2half_rn(j < NCLASS ? W2[k * NCLASS + j] : 0.0f);
    }
}

__global__ void cvt_x_kernel(const float* __restrict__ x) {
    size_t i = (size_t)blockIdx.x * blockDim.x + threadIdx.x;   // over NN*NFEAT/8
    if (i >= (size_t)NN * NFEAT / 8) return;
    const float4* p = (const float4*)x + i * 2;
    float4 a = p[0], b = p[1];
    uint4 u = make_uint4(h2u(__floats2half2_rn(a.x, a.y)), h2u(__floats2half2_rn(a.z, a.w)),
                         h2u(__floats2half2_rn(b.x, b.y)), h2u(__floats2half2_rn(b.z, b.w)));
    ((uint4*)g_xh)[i] = u;
}

// ---------------- CSR build ----------------
__global__ void hist_kernel(const int* __restrict__ dst) {
    int e = blockIdx.x * blockDim.x + threadIdx.x;
    if (e < EE) atomicAdd(&g_cnt[dst[e]], 1);
}

__global__ __launch_bounds__(1024) void scan_kernel() {
    __shared__ int sums[1024];
    const int T = 1024;
    const int IT = (NN + T - 1) / T;
    int t = threadIdx.x;
    int base = t * IT;
    int s = 0;
    for (int i = 0; i < IT; i++) {
        int idx = base + i;
        if (idx < NN) s += g_cnt[idx];
    }
    sums[t] = s;
    __syncthreads();
    for (int off = 1; off < T; off <<= 1) {
        int v = (t >= off) ? sums[t - off] : 0;
        __syncthreads();
        sums[t] += v;
        __syncthreads();
    }
    int run = sums[t] - s;
    for (int i = 0; i < IT; i++) {
        int idx = base + i;
        if (idx < NN) {
            g_rowptr[idx] = run;
            g_cursor[idx] = run;
            run += g_cnt[idx];
        }
    }
    if (t == T - 1) g_rowptr[NN] = sums[T - 1];
}

__global__ void scatter_kernel(const int* __restrict__ src,
                               const int* __restrict__ dst,
                               const float* __restrict__ w) {
    int e = blockIdx.x * blockDim.x + threadIdx.x;
    if (e < EE) {
        int d = dst[e];
        int p = atomicAdd(&g_cursor[d], 1);
        g_esrc[p] = src[e];
        g_ew[p]   = w[e];
    }
}

// =========================================================================
// GEMM1 (fp16 HMMA, cp.async double-buffered): g_support1h = fp16(x @ W1)
// M=NP, K=512, N=256. BM=128, BN=128, BK=32, 8 warps (2x4), warp 64x32.
// Pure fp16 operands; no in-loop conversion.
// =========================================================================
__global__ __launch_bounds__(256) void gemm1_tc() {
    __shared__ __half As[2][128][40];
    __shared__ __half Bs[2][32][136];
    const int t   = threadIdx.x;
    const int wid = t >> 5;
    const int wr  = wid >> 2;     // 0..1
    const int wc  = wid & 3;      // 0..3
    const int row0 = blockIdx.y * 128;
    const int col0 = blockIdx.x * 128;

    wmma::fragment<wmma::accumulator, 16, 16, 16, float> acc[4][2];
#pragma unroll
    for (int i = 0; i < 4; i++)
#pragma unroll
        for (int j = 0; j < 2; j++) wmma::fill_fragment(acc[i][j], 0.0f);

    const int arow = t >> 1;          // 0..127
    const int ac16 = (t & 1) * 16;    // 0/16
    const int brow = t >> 3;          // 0..31
    const int bc16 = (t & 7) * 16;    // 0..112
    int garow = row0 + arow; if (garow >= NN) garow = NN - 1;
    const __half* Ap = g_xh + (size_t)garow * NFEAT;
    const __half* Bp = g_w1h + col0 + bc16;

    const int NIT = NFEAT / 32;   // 16
    // preload stage 0
    cp_async16(&As[0][arow][ac16],     Ap + ac16);
    cp_async16(&As[0][arow][ac16 + 8], Ap + ac16 + 8);
    cp_async16(&Bs[0][brow][bc16],     Bp + (size_t)brow * NHID);
    cp_async16(&Bs[0][brow][bc16 + 8], Bp + (size_t)brow * NHID + 8);
    cp_commit();

    for (int i = 0; i < NIT; i++) {
        if (i + 1 < NIT) {
            int k1 = (i + 1) * 32;
            int nb = (i + 1) & 1;
            cp_async16(&As[nb][arow][ac16],     Ap + k1 + ac16);
            cp_async16(&As[nb][arow][ac16 + 8], Ap + k1 + ac16 + 8);
            cp_async16(&Bs[nb][brow][bc16],     Bp + (size_t)(k1 + brow) * NHID);
            cp_async16(&Bs[nb][brow][bc16 + 8], Bp + (size_t)(k1 + brow) * NHID + 8);
            cp_commit();
            cp_wait1();
        } else {
            cp_wait0();
        }
        __syncthreads();
        int cb = i & 1;
#pragma unroll
        for (int kk = 0; kk < 32; kk += 16) {
            wmma::fragment<wmma::matrix_a, 16, 16, 16, __half, wmma::row_major> af[4];
            wmma::fragment<wmma::matrix_b, 16, 16, 16, __half, wmma::row_major> bf[2];
#pragma unroll
            for (int ii = 0; ii < 4; ii++)
                wmma::load_matrix_sync(af[ii], &As[cb][wr * 64 + ii * 16][kk], 40);
#pragma unroll
            for (int j = 0; j < 2; j++)
                wmma::load_matrix_sync(bf[j], &Bs[cb][kk][wc * 32 + j * 16], 136);
#pragma unroll
            for (int ii = 0; ii < 4; ii++)
#pragma unroll
                for (int j = 0; j < 2; j++)
                    wmma::mma_sync(acc[ii][j], af[ii], bf[j], acc[ii][j]);
        }
        __syncthreads();
    }

    // fp16 epilogue via smem staging (reuse As)
    float* stage = (float*)&As[0][0][0] + wid * 320;
    const int L = t & 31;
    const int rr = L >> 1;
    const int cc = (L & 1) * 8;
#pragma unroll
    for (int i = 0; i < 4; i++)
#pragma unroll
        for (int j = 0; j < 2; j++) {
            wmma::store_matrix_sync(stage, acc[i][j], 20, wmma::mem_row_major);
            __syncwarp();
            const float* sp = stage + rr * 20 + cc;
            __half2 h0 = __floats2half2_rn(sp[0], sp[1]);
            __half2 h1 = __floats2half2_rn(sp[2], sp[3]);
            __half2 h2 = __floats2half2_rn(sp[4], sp[5]);
            __half2 h3 = __floats2half2_rn(sp[6], sp[7]);
            int gr = row0 + wr * 64 + i * 16 + rr;
            int gc = col0 + wc * 32 + j * 16 + cc;
            *(uint4*)(g_support1h + (size_t)gr * NHID + gc) =
                make_uint4(h2u(h0), h2u(h1), h2u(h2), h2u(h3));
            __syncwarp();
        }
}

// =========================================================================
// zgemm (fp16 HMMA, cp.async double-buffered): g_tmp = h1 @ [Wmu|Wlv]
// M=NP, K=256, N=128.
// =========================================================================
__global__ __launch_bounds__(256) void zgemm_tc() {
    __shared__ __half As[2][128][40];
    __shared__ __half Bs[2][32][136];
    const int t   = threadIdx.x;
    const int wid = t >> 5;
    const int wr  = wid >> 2;
    const int wc  = wid & 3;
    const int row0 = blockIdx.x * 128;

    wmma::fragment<wmma::accumulator, 16, 16, 16, float> acc[4][2];
#pragma unroll
    for (int i = 0; i < 4; i++)
#pragma unroll
        for (int j = 0; j < 2; j++) wmma::fill_fragment(acc[i][j], 0.0f);

    const int arow = t >> 1;
    const int ac16 = (t & 1) * 16;
    const int brow = t >> 3;
    const int bc16 = (t & 7) * 16;
    int garow = row0 + arow; if (garow >= NN) garow = NN - 1;
    const __half* Ap = g_h1h + (size_t)garow * NHID;
    const __half* Bp = g_wmlh + bc16;

    const int NIT = NHID / 32;   // 8
    cp_async16(&As[0][arow][ac16],     Ap + ac16);
    cp_async16(&As[0][arow][ac16 + 8], Ap + ac16 + 8);
    cp_async16(&Bs[0][brow][bc16],     Bp + (size_t)brow * 128);
    cp_async16(&Bs[0][brow][bc16 + 8], Bp + (size_t)brow * 128 + 8);
    cp_commit();

    for (int i = 0; i < NIT; i++) {
        if (i + 1 < NIT) {
            int k1 = (i + 1) * 32;
            int nb = (i + 1) & 1;
            cp_async16(&As[nb][arow][ac16],     Ap + k1 + ac16);
            cp_async16(&As[nb][arow][ac16 + 8], Ap + k1 + ac16 + 8);
            cp_async16(&Bs[nb][brow][bc16],     Bp + (size_t)(k1 + brow) * 128);
            cp_async16(&Bs[nb][brow][bc16 + 8], Bp + (size_t)(k1 + brow) * 128 + 8);
            cp_commit();
            cp_wait1();
        } else {
            cp_wait0();
        }
        __syncthreads();
        int cb = i & 1;
#pragma unroll
        for (int kk = 0; kk < 32; kk += 16) {
            wmma::fragment<wmma::matrix_a, 16, 16, 16, __half, wmma::row_major> af[4];
            wmma::fragment<wmma::matrix_b, 16, 16, 16, __half, wmma::row_major> bf[2];
#pragma unroll
            for (int ii = 0; ii < 4; ii++)
                wmma::load_matrix_sync(af[ii], &As[cb][wr * 64 + ii * 16][kk], 40);
#pragma unroll
            for (int j = 0; j < 2; j++)
                wmma::load_matrix_sync(bf[j], &Bs[cb][kk][wc * 32 + j * 16], 136);
#pragma unroll
            for (int ii = 0; ii < 4; ii++)
#pragma unroll
                for (int j = 0; j < 2; j++)
                    wmma::mma_sync(acc[ii][j], af[ii], bf[j], acc[ii][j]);
        }
        __syncthreads();
    }
#pragma unroll
    for (int i = 0; i < 4; i++)
#pragma unroll
        for (int j = 0; j < 2; j++) {
            int r = row0 + wr * 64 + i * 16;
            int c = wc * 32 + j * 16;
            wmma::store_matrix_sync(g_tmp + (size_t)r * 128 + c, acc[i][j],
                                    128, wmma::mem_row_major);
        }
}

// =========================================================================
// dec gemm (fp16 HMMA): g_x1h = fp16(relu(z @ Wdec + bdec)), z on the fly:
//   z = (mu + bmu) + eps * exp(lv + blv). bdec+relu fused into epilogue.
// M=NP, K=64, N=256. grid (2, NP/128)
// =========================================================================
__global__ __launch_bounds__(256) void dec_tc(const float* __restrict__ bmu,
                                              const float* __restrict__ blv,
                                              const float* __restrict__ eps,
                                              const float* __restrict__ bdec) {
    __shared__ __half As[128][40];
    __shared__ __half Bs[32][136];
    const int t   = threadIdx.x;
    const int wid = t >> 5;
    const int wr  = wid >> 2;
    const int wc  = wid & 3;
    const int row0 = blockIdx.y * 128;
    const int col0 = blockIdx.x * 128;

    wmma::fragment<wmma::accumulator, 16, 16, 16, float> acc[4][2];
#pragma unroll
    for (int i = 0; i < 4; i++)
#pragma unroll
        for (int j = 0; j < 2; j++) wmma::fill_fragment(acc[i][j], 0.0f);

    const int arow = t >> 1;
    const int ac16 = (t & 1) * 16;
    const int brow = t >> 3;
    const int bc16 = (t & 7) * 16;
    int garow = row0 + arow; if (garow >= NN) garow = NN - 1;
    const float* Mp = g_tmp + (size_t)garow * 128;
    const float* Ep = eps + (size_t)garow * NCODE;

    for (int k0 = 0; k0 < NCODE; k0 += 32) {
        {
            float z[16];
#pragma unroll
            for (int h = 0; h < 4; h++) {
                int c = k0 + ac16 + h * 4;
                float4 m  = *(const float4*)(Mp + c);
                float4 l  = *(const float4*)(Mp + 64 + c);
                float4 e  = *(const float4*)(Ep + c);
                float4 bm = *(const float4*)(bmu + c);
                float4 bl = *(const float4*)(blv + c);
                z[h * 4 + 0] = (m.x + bm.x) + e.x * expf(l.x + bl.x);
                z[h * 4 + 1] = (m.y + bm.y) + e.y * expf(l.y + bl.y);
                z[h * 4 + 2] = (m.z + bm.z) + e.z * expf(l.z + bl.z);
                z[h * 4 + 3] = (m.w + bm.w) + e.w * expf(l.w + bl.w);
            }
            uint4 u0 = make_uint4(h2u(__floats2half2_rn(z[0], z[1])),
                                  h2u(__floats2half2_rn(z[2], z[3])),
                                  h2u(__floats2half2_rn(z[4], z[5])),
                                  h2u(__floats2half2_rn(z[6], z[7])));
            uint4 u1 = make_uint4(h2u(__floats2half2_rn(z[8], z[9])),
                                  h2u(__floats2half2_rn(z[10], z[11])),
                                  h2u(__floats2half2_rn(z[12], z[13])),
                                  h2u(__floats2half2_rn(z[14], z[15])));
            *(uint4*)&As[arow][ac16]     = u0;
            *(uint4*)&As[arow][ac16 + 8] = u1;
            const __half* bp = g_wdech + (size_t)(k0 + brow) * NHID + col0 + bc16;
            *(uint4*)&Bs[brow][bc16]     = *(const uint4*)(bp);
            *(uint4*)&Bs[brow][bc16 + 8] = *(const uint4*)(bp + 8);
        }
        __syncthreads();
#pragma unroll
        for (int kk = 0; kk < 32; kk += 16) {
            wmma::fragment<wmma::matrix_a, 16, 16, 16, __half, wmma::row_major> af[4];
            wmma::fragment<wmma::matrix_b, 16, 16, 16, __half, wmma::row_major> bf[2];
#pragma unroll
            for (int i = 0; i < 4; i++)
                wmma::load_matrix_sync(af[i], &As[wr * 64 + i * 16][kk], 40);
#pragma unroll
            for (int j = 0; j < 2; j++)
                wmma::load_matrix_sync(bf[j], &Bs[kk][wc * 32 + j * 16], 136);
#pragma unroll
            for (int i = 0; i < 4; i++)
#pragma unroll
                for (int j = 0; j < 2; j++)
                    wmma::mma_sync(acc[i][j], af[i], bf[j], acc[i][j]);
        }
        __syncthreads();
    }

    // epilogue: + bdec, relu, fp16
    float* stage = (float*)&As[0][0] + wid * 320;
    const int L = t & 31;
    const int rr = L >> 1;
    const int cc = (L & 1) * 8;
#pragma unroll
    for (int i = 0; i < 4; i++)
#pragma unroll
        for (int j = 0; j < 2; j++) {
            wmma::store_matrix_sync(stage, acc[i][j], 20, wmma::mem_row_major);
            __syncwarp();
            const float* sp = stage + rr * 20 + cc;
            int gr = row0 + wr * 64 + i * 16 + rr;
            int gc = col0 + wc * 32 + j * 16 + cc;
            float4 bd0 = *(const float4*)(bdec + gc);
            float4 bd1 = *(const float4*)(bdec + gc + 4);
            float v0 = fmaxf(sp[0] + bd0.x, 0.f), v1 = fmaxf(sp[1] + bd0.y, 0.f);
            float v2 = fmaxf(sp[2] + bd0.z, 0.f), v3 = fmaxf(sp[3] + bd0.w, 0.f);
            float v4 = fmaxf(sp[4] + bd1.x, 0.f), v5 = fmaxf(sp[5] + bd1.y, 0.f);
            float v6 = fmaxf(sp[6] + bd1.z, 0.f), v7 = fmaxf(sp[7] + bd1.w, 0.f);
            *(uint4*)(g_x1h + (size_t)gr * NHID + gc) =
                make_uint4(h2u(__floats2half2_rn(v0, v1)), h2u(__floats2half2_rn(v2, v3)),
                           h2u(__floats2half2_rn(v4, v5)), h2u(__floats2half2_rn(v6, v7)));
            __syncwarp();
        }
}

// =========================================================================
// out gemm (fp16 HMMA): g_support2 = [x1 ; h1] @ W2   (x1 already relu'd)
// M=NP, K=512, N=64 (pre-padded). 8 warps (4x2), warp 32x32. BK=32.
// Pure fp16 copies for A and B.
// =========================================================================
__global__ __launch_bounds__(256) void out_tc() {
    __shared__ __half As[128][40];
    __shared__ __half Bs[32][72];
    const int t   = threadIdx.x;
    const int wid = t >> 5;
    const int wr  = wid >> 1;     // 0..3
    const int wc  = wid & 1;      // 0..1
    const int row0 = blockIdx.x * 128;

    wmma::fragment<wmma::accumulator, 16, 16, 16, float> acc[2][2];
#pragma unroll
    for (int i = 0; i < 2; i++)
#pragma unroll
        for (int j = 0; j < 2; j++) wmma::fill_fragment(acc[i][j], 0.0f);

    const int arow = t >> 1;
    const int ac16 = (t & 1) * 16;
    const int brow = t >> 3;          // 0..31
    const int bc8  = (t & 7) * 8;     // 0..56
    int garow = row0 + arow; if (garow >= NN) garow = NN - 1;
    const __half* Ap1 = g_x1h + (size_t)garow * NHID;
    const __half* Ap2 = g_h1h + (size_t)garow * NHID;

    for (int k0 = 0; k0 < 2 * NHID; k0 += 32) {
        {
            const __half* ap = (k0 < NHID) ? (Ap1 + k0 + ac16)
                                           : (Ap2 + (k0 - NHID) + ac16);
            *(uint4*)&As[arow][ac16]     = *(const uint4*)(ap);
            *(uint4*)&As[arow][ac16 + 8] = *(const uint4*)(ap + 8);
            *(uint4*)&Bs[brow][bc8] =
                *(const uint4*)(g_w2h + (size_t)(k0 + brow) * 64 + bc8);
        }
        __syncthreads();
#pragma unroll
        for (int kk = 0; kk < 32; kk += 16) {
            wmma::fragment<wmma::matrix_a, 16, 16, 16, __half, wmma::row_major> af[2];
            wmma::fragment<wmma::matrix_b, 16, 16, 16, __half, wmma::row_major> bf[2];
#pragma unroll
            for (int i = 0; i < 2; i++)
                wmma::load_matrix_sync(af[i], &As[wr * 32 + i * 16][kk], 40);
#pragma unroll
            for (int j = 0; j < 2; j++)
                wmma::load_matrix_sync(bf[j], &Bs[kk][wc * 32 + j * 16], 72);
#pragma unroll
            for (int i = 0; i < 2; i++)
#pragma unroll
                for (int j = 0; j < 2; j++)
                    wmma::mma_sync(acc[i][j], af[i], bf[j], acc[i][j]);
        }
        __syncthreads();
    }
#pragma unroll
    for (int i = 0; i < 2; i++)
#pragma unroll
        for (int j = 0; j < 2; j++) {
            int r = row0 + wr * 32 + i * 16;
            int c = wc * 32 + j * 16;
            wmma::store_matrix_sync(g_support2 + (size_t)r * 64 + c, acc[i][j],
                                    64, wmma::mem_row_major);
        }
}

// ---------------- spmm1 + bias + relu (fp16 gather -> fp16 h1) -----------
__global__ void spmm_relu_kernel(const float* __restrict__ b1) {
    int warp = (blockIdx.x * blockDim.x + threadIdx.x) >> 5;
    int lane = threadIdx.x & 31;
    if (warp >= NN) return;
    int beg = g_rowptr[warp];
    int end = g_rowptr[warp + 1];
    float acc[8] = {0, 0, 0, 0, 0, 0, 0, 0};
    const int co = lane * 8;
    int e = beg;
    for (; e + 4 <= end; e += 4) {
        int   s0 = g_esrc[e],   s1 = g_esrc[e + 1], s2 = g_esrc[e + 2], s3 = g_esrc[e + 3];
        float w0 = g_ew[e],     w1 = g_ew[e + 1],   w2 = g_ew[e + 2],   w3 = g_ew[e + 3];
        uint4 u0 = *(const uint4*)(g_support1h + (size_t)s0 * NHID + co);
        uint4 u1 = *(const uint4*)(g_support1h + (size_t)s1 * NHID + co);
        uint4 u2 = *(const uint4*)(g_support1h + (size_t)s2 * NHID + co);
        uint4 u3 = *(const uint4*)(g_support1h + (size_t)s3 * NHID + co);
        __half2* h0 = (__half2*)&u0;
        __half2* h1 = (__half2*)&u1;
        __half2* h2 = (__half2*)&u2;
        __half2* h3 = (__half2*)&u3;
#pragma unroll
        for (int q = 0; q < 4; q++) {
            float2 f0 = __half22float2(h0[q]);
            float2 f1 = __half22float2(h1[q]);
            float2 f2 = __half22float2(h2[q]);
            float2 f3 = __half22float2(h3[q]);
            acc[2 * q]     += w0 * f0.x + w1 * f1.x + w2 * f2.x + w3 * f3.x;
            acc[2 * q + 1] += w0 * f0.y + w1 * f1.y + w2 * f2.y + w3 * f3.y;
        }
    }
    for (; e < end; e++) {
        int s = g_esrc[e];
        float w = g_ew[e];
        uint4 u = *(const uint4*)(g_support1h + (size_t)s * NHID + co);
        __half2* h = (__half2*)&u;
#pragma unroll
        for (int q = 0; q < 4; q++) {
            float2 f = __half22float2(h[q]);
            acc[2 * q]     += w * f.x;
            acc[2 * q + 1] += w * f.y;
        }
    }
    float4 bb0 = *(const float4*)(b1 + co);
    float4 bb1 = *(const float4*)(b1 + co + 4);
    float o[8];
    o[0] = fmaxf(acc[0] + bb0.x, 0.f); o[1] = fmaxf(acc[1] + bb0.y, 0.f);
    o[2] = fmaxf(acc[2] + bb0.z, 0.f); o[3] = fmaxf(acc[3] + bb0.w, 0.f);
    o[4] = fmaxf(acc[4] + bb1.x, 0.f); o[5] = fmaxf(acc[5] + bb1.y, 0.f);
    o[6] = fmaxf(acc[6] + bb1.z, 0.f); o[7] = fmaxf(acc[7] + bb1.w, 0.f);
    uint4 u = make_uint4(h2u(__floats2half2_rn(o[0], o[1])),
                         h2u(__floats2half2_rn(o[2], o[3])),
                         h2u(__floats2half2_rn(o[4], o[5])),
                         h2u(__floats2half2_rn(o[6], o[7])));
    *(uint4*)(g_h1h + (size_t)warp * NHID + co) = u;
}

// ---------------- spmm2 + b2 + log_softmax -> out ----------------
__global__ void spmm_softmax_kernel(const float* __restrict__ b2,
                                    float* __restrict__ out) {
    int warp = (blockIdx.x * blockDim.x + threadIdx.x) >> 5;
    int lane = threadIdx.x & 31;
    if (warp >= NN) return;
    int beg = g_rowptr[warp];
    int end = g_rowptr[warp + 1];
    bool active = lane < 10;
    float4 acc = make_float4(0, 0, 0, 0);
    const float4* S = (const float4*)g_support2;   // stride 16 float4 / row
    for (int e = beg; e < end; e++) {
        int s = g_esrc[e];
        float w = g_ew[e];
        if (active) {
            float4 v = __ldg(S + (size_t)s * 16 + lane);
            acc.x += w * v.x; acc.y += w * v.y; acc.z += w * v.z; acc.w += w * v.w;
        }
    }
    float4 v = make_float4(-INFINITY, -INFINITY, -INFINITY, -INFINITY);
    if (active) {
        float4 b = ((const float4*)b2)[lane];
        v.x = acc.x + b.x; v.y = acc.y + b.y; v.z = acc.z + b.z; v.w = acc.w + b.w;
    }
    float m = fmaxf(fmaxf(v.x, v.y), fmaxf(v.z, v.w));
#pragma unroll
    for (int off = 16; off > 0; off >>= 1)
        m = fmaxf(m, __shfl_xor_sync(0xFFFFFFFFu, m, off));
    float s = active ? (expf(v.x - m) + expf(v.y - m) + expf(v.z - m) + expf(v.w - m)) : 0.0f;
#pragma unroll
    for (int off = 16; off > 0; off >>= 1)
        s += __shfl_xor_sync(0xFFFFFFFFu, s, off);
    float lse = m + logf(s);
    if (active) {
        float4 o;
        o.x = v.x - lse; o.y = v.y - lse; o.z = v.z - lse; o.w = v.w - lse;
        ((float4*)out)[(size_t)warp * 10 + lane] = o;
    }
}

// ---------------- launch ----------------
extern "C" void kernel_launch(void* const* d_in, const int* in_sizes, int n_in,
                              void* d_out, int out_size) {
    const float* x        = (const float*)d_in[0];
    const int*   edge_src = (const int*)  d_in[1];
    const int*   edge_dst = (const int*)  d_in[2];
    const float* edge_w   = (const float*)d_in[3];
    const float* eps      = (const float*)d_in[4];
    const float* W1       = (const float*)d_in[5];
    const float* b1       = (const float*)d_in[6];
    const float* W_mu     = (const float*)d_in[7];
    const float* b_mu     = (const float*)d_in[8];
    const float* W_lv     = (const float*)d_in[9];
    const float* b_lv     = (const float*)d_in[10];
    const float* W_dec    = (const float*)d_in[11];
    const float* b_dec    = (const float*)d_in[12];
    const float* W2       = (const float*)d_in[13];
    const float* b2       = (const float*)d_in[14];
    float* out = (float*)d_out;

    // zero counts via async memset
    void* cnt_ptr = nullptr;
    cudaGetSymbolAddress(&cnt_ptr, g_cnt);
    cudaMemsetAsync(cnt_ptr, 0, NN * sizeof(int));

    // kernel index:  0      1      2     3 (ncu window)  4     5
    cvt_w_kernel<<<(NFEAT * NHID + 255) / 256, 256>>>(W1, W_mu, W_lv, W_dec, W2);  // 0
    cvt_x_kernel<<<((size_t)NN * NFEAT / 8 + 255) / 256, 256>>>(x);                // 1
    hist_kernel<<<(EE + 255) / 256, 256>>>(edge_dst);                              // 2
    gemm1_tc<<<dim3(NHID / 128, NP / 128), 256>>>();                               // 3
    scan_kernel<<<1, 1024>>>();                                                    // 4
    scatter_kernel<<<(EE + 255) / 256, 256>>>(edge_src, edge_dst, edge_w);         // 5

    // h1(fp16) = relu(spmm + b1)
    spmm_relu_kernel<<<(NN * 32 + 255) / 256, 256>>>(b1);

    // tmp = h1 @ [Wmu|Wlv]
    zgemm_tc<<<NP / 128, 256>>>();

    // x1(fp16) = relu(z @ Wdec + bdec), z on the fly
    dec_tc<<<dim3(NHID / 128, NP / 128), 256>>>(b_mu, b_lv, eps, b_dec);

    // support2 = [x1; h1] @ W2
    out_tc<<<NP / 128, 256>>>();

    // out = log_softmax(spmm + b2)
    spmm_softmax_kernel<<<(NN * 32 + 255) / 256, 256>>>(b2, out);
}

// round 12
// speedup vs baseline: 1.3066x; 1.0629x over previous
#include <cuda_runtime.h>
#include <mma.h>
#include <math.h>
#include <stdint.h>
#include <cuda_fp16.h>

using namespace nvcuda;

#define NN      50000
#define NP      50048            // NN padded to multiple of 128
#define EE      800000
#define NFEAT   512
#define NHID    256
#define NCODE   64
#define NCLASS  40

// ---------------- device scratch (static, allocation-free) ----------------
__device__ __align__(16) __half g_xh  [(size_t)NN * NFEAT];     // fp16(x)
__device__ __align__(16) __half g_w1h [NFEAT * NHID];           // fp16(W1)
__device__ __align__(16) __half g_wmlh[NHID * 128];             // fp16([Wmu|Wlv])
__device__ __align__(16) __half g_wdech[NCODE * NHID];          // fp16(Wdec)
__device__ __align__(16) __half g_w2h [2 * NHID * 64];          // fp16(W2) padded cols
__device__ __align__(16) __half g_support1h[(size_t)NP * NHID]; // x @ W1 (fp16)
__device__ __align__(16) __half g_h1h[(size_t)NP * NHID];       // relu(spmm + b1) fp16
__device__ __align__(16) __half g_x1h[(size_t)NP * NHID];       // relu(z @ Wdec + bdec) fp16
__device__ float g_support2[(size_t)NP * 64];     // concat @ W2 (padded cols)
__device__ int   g_cnt   [NN];
__device__ int   g_rowptr[NN + 1];
__device__ int   g_cursor[NN];
__device__ int   g_esrc[EE];
__device__ float g_ew  [EE];

__device__ __forceinline__ unsigned h2u(__half2 h) {
    return *(unsigned*)&h;
}

__device__ __forceinline__ void cp_async16(void* smem, const void* gmem) {
    unsigned int s = (unsigned int)__cvta_generic_to_shared(smem);
    asm volatile("cp.async.cg.shared.global [%0], [%1], 16;" :: "r"(s), "l"(gmem));
}
__device__ __forceinline__ void cp_commit() {
    asm volatile("cp.async.commit_group;");
}
__device__ __forceinline__ void cp_wait1() {
    asm volatile("cp.async.wait_group 1;");
}
__device__ __forceinline__ void cp_wait0() {
    asm volatile("cp.async.wait_group 0;");
}

// ---------------- fp16 conversion kernels ----------------
__global__ void cvt_w_kernel(const float* __restrict__ W1,
                             const float* __restrict__ Wmu,
                             const float* __restrict__ Wlv,
                             const float* __restrict__ Wdec,
                             const float* __restrict__ W2) {
    int i = blockIdx.x * blockDim.x + threadIdx.x;
    if (i < NFEAT * NHID) g_w1h[i] = __float2half_rn(W1[i]);
    if (i < NHID * 128) {
        int k = i >> 7, j = i & 127;
        float v = (j < 64) ? Wmu[k * NCODE + j] : Wlv[k * NCODE + (j - 64)];
        g_wmlh[i] = __float2half_rn(v);
    }
    if (i < NCODE * NHID) g_wdech[i] = __float2half_rn(Wdec[i]);
    if (i < 2 * NHID * 64) {
        int k = i >> 6, j = i & 63;
        g_w2h[i] = __float2half_rn(j < NCLASS ? W2[k * NCLASS + j] : 0.0f);
    }
}

__global__ void cvt_x_kernel(const float* __restrict__ x) {
    size_t i = (size_t)blockIdx.x * blockDim.x + threadIdx.x;   // over NN*NFEAT/8
    if (i >= (size_t)NN * NFEAT / 8) return;
    const float4* p = (const float4*)x + i * 2;
    float4 a = p[0], b = p[1];
    uint4 u = make_uint4(h2u(__floats2half2_rn(a.x, a.y)), h2u(__floats2half2_rn(a.z, a.w)),
                         h2u(__floats2half2_rn(b.x, b.y)), h2u(__floats2half2_rn(b.z, b.w)));
    ((uint4*)g_xh)[i] = u;
}

// ---------------- CSR build ----------------
__global__ void hist_kernel(const int* __restrict__ dst) {
    int e = blockIdx.x * blockDim.x + threadIdx.x;
    if (e < EE) atomicAdd(&g_cnt[dst[e]], 1);
}

__global__ __launch_bounds__(1024) void scan_kernel() {
    __shared__ int sums[1024];
    const int T = 1024;
    const int IT = (NN + T - 1) / T;
    int t = threadIdx.x;
    int base = t * IT;
    int s = 0;
    for (int i = 0; i < IT; i++) {
        int idx = base + i;
        if (idx < NN) s += g_cnt[idx];
    }
    sums[t] = s;
    __syncthreads();
    for (int off = 1; off < T; off <<= 1) {
        int v = (t >= off) ? sums[t - off] : 0;
        __syncthreads();
        sums[t] += v;
        __syncthreads();
    }
    int run = sums[t] - s;
    for (int i = 0; i < IT; i++) {
        int idx = base + i;
        if (idx < NN) {
            g_rowptr[idx] = run;
            g_cursor[idx] = run;
            run += g_cnt[idx];
        }
    }
    if (t == T - 1) g_rowptr[NN] = sums[T - 1];
}

__global__ void scatter_kernel(const int* __restrict__ src,
                               const int* __restrict__ dst,
                               const float* __restrict__ w) {
    int e = blockIdx.x * blockDim.x + threadIdx.x;
    if (e < EE) {
        int d = dst[e];
        int p = atomicAdd(&g_cursor[d], 1);
        g_esrc[p] = src[e];
        g_ew[p]   = w[e];
    }
}

// =========================================================================
// GEMM1 (fp16 HMMA, cp.async double-buffered): g_support1h = fp16(x @ W1)
// M=NP, K=512, N=256. BM=128, BN=128, BK=32, 8 warps (2x4), warp 64x32.
// =========================================================================
__global__ __launch_bounds__(256) void gemm1_tc() {
    __shared__ __half As[2][128][40];
    __shared__ __half Bs[2][32][136];
    const int t   = threadIdx.x;
    const int wid = t >> 5;
    const int wr  = wid >> 2;     // 0..1
    const int wc  = wid & 3;      // 0..3
    const int row0 = blockIdx.y * 128;
    const int col0 = blockIdx.x * 128;

    wmma::fragment<wmma::accumulator, 16, 16, 16, float> acc[4][2];
#pragma unroll
    for (int i = 0; i < 4; i++)
#pragma unroll
        for (int j = 0; j < 2; j++) wmma::fill_fragment(acc[i][j], 0.0f);

    const int arow = t >> 1;          // 0..127
    const int ac16 = (t & 1) * 16;    // 0/16
    const int brow = t >> 3;          // 0..31
    const int bc16 = (t & 7) * 16;    // 0..112
    int garow = row0 + arow; if (garow >= NN) garow = NN - 1;
    const __half* Ap = g_xh + (size_t)garow * NFEAT;
    const __half* Bp = g_w1h + col0 + bc16;

    const int NIT = NFEAT / 32;   // 16
    cp_async16(&As[0][arow][ac16],     Ap + ac16);
    cp_async16(&As[0][arow][ac16 + 8], Ap + ac16 + 8);
    cp_async16(&Bs[0][brow][bc16],     Bp + (size_t)brow * NHID);
    cp_async16(&Bs[0][brow][bc16 + 8], Bp + (size_t)brow * NHID + 8);
    cp_commit();

    for (int i = 0; i < NIT; i++) {
        if (i + 1 < NIT) {
            int k1 = (i + 1) * 32;
            int nb = (i + 1) & 1;
            cp_async16(&As[nb][arow][ac16],     Ap + k1 + ac16);
            cp_async16(&As[nb][arow][ac16 + 8], Ap + k1 + ac16 + 8);
            cp_async16(&Bs[nb][brow][bc16],     Bp + (size_t)(k1 + brow) * NHID);
            cp_async16(&Bs[nb][brow][bc16 + 8], Bp + (size_t)(k1 + brow) * NHID + 8);
            cp_commit();
            cp_wait1();
        } else {
            cp_wait0();
        }
        __syncthreads();
        int cb = i & 1;
#pragma unroll
        for (int kk = 0; kk < 32; kk += 16) {
            wmma::fragment<wmma::matrix_a, 16, 16, 16, __half, wmma::row_major> af[4];
            wmma::fragment<wmma::matrix_b, 16, 16, 16, __half, wmma::row_major> bf[2];
#pragma unroll
            for (int ii = 0; ii < 4; ii++)
                wmma::load_matrix_sync(af[ii], &As[cb][wr * 64 + ii * 16][kk], 40);
#pragma unroll
            for (int j = 0; j < 2; j++)
                wmma::load_matrix_sync(bf[j], &Bs[cb][kk][wc * 32 + j * 16], 136);
#pragma unroll
            for (int ii = 0; ii < 4; ii++)
#pragma unroll
                for (int j = 0; j < 2; j++)
                    wmma::mma_sync(acc[ii][j], af[ii], bf[j], acc[ii][j]);
        }
        __syncthreads();
    }

    float* stage = (float*)&As[0][0][0] + wid * 320;
    const int L = t & 31;
    const int rr = L >> 1;
    const int cc = (L & 1) * 8;
#pragma unroll
    for (int i = 0; i < 4; i++)
#pragma unroll
        for (int j = 0; j < 2; j++) {
            wmma::store_matrix_sync(stage, acc[i][j], 20, wmma::mem_row_major);
            __syncwarp();
            const float* sp = stage + rr * 20 + cc;
            __half2 h0 = __floats2half2_rn(sp[0], sp[1]);
            __half2 h1 = __floats2half2_rn(sp[2], sp[3]);
            __half2 h2 = __floats2half2_rn(sp[4], sp[5]);
            __half2 h3 = __floats2half2_rn(sp[6], sp[7]);
            int gr = row0 + wr * 64 + i * 16 + rr;
            int gc = col0 + wc * 32 + j * 16 + cc;
            *(uint4*)(g_support1h + (size_t)gr * NHID + gc) =
                make_uint4(h2u(h0), h2u(h1), h2u(h2), h2u(h3));
            __syncwarp();
        }
}

// =========================================================================
// zdec fused: phase1 tmp = h1 @ [Wmu|Wlv] (regs);
// phase z: z = (mu+bmu) + eps*exp(lv+blv) via smem exchange (fp16 tile);
// phase2: x1 = relu(z @ Wdec + bdec) -> g_x1h.
// M=NP per 128-row block. Dynamic smem arena.
// =========================================================================
__global__ __launch_bounds__(256) void zdec_tc(const float* __restrict__ bmu,
                                               const float* __restrict__ blv,
                                               const float* __restrict__ eps,
                                               const float* __restrict__ bdec) {
    extern __shared__ char arena[];
    // phase1 buffers
    __half (*hA)[128][40]  = (__half (*)[128][40])arena;            // 20480 B
    __half (*hB)[32][136]  = (__half (*)[32][136])(arena + 20480);  // 17408 B
    // phase z / 2 buffers (alias phase1 region after it's dead)
    float*  lv_s  = (float*)arena;                   // [128][68]  34816 B
    __half* z_s   = (__half*)(arena + 34816);        // [128][72]  18432 B
    float*  stg   = (float*)(arena + 53248);         // 8 * 320 floats
    __half* bB    = (__half*)arena;                  // [64][136]  17408 B (phase2)

    const int t   = threadIdx.x;
    const int wid = t >> 5;
    const int wr  = wid >> 2;     // 0..1
    const int wc  = wid & 3;      // 0..3
    const int row0 = blockIdx.x * 128;
    const int L  = t & 31;
    const int rr = L >> 1;
    const int cc = (L & 1) * 8;

    wmma::fragment<wmma::accumulator, 16, 16, 16, float> acc[4][2];
#pragma unroll
    for (int i = 0; i < 4; i++)
#pragma unroll
        for (int j = 0; j < 2; j++) wmma::fill_fragment(acc[i][j], 0.0f);

    // ---- phase 1: tmp = h1 @ [Wmu|Wlv], K=256, N=128 ----
    {
        const int arow = t >> 1;
        const int ac16 = (t & 1) * 16;
        const int brow = t >> 3;
        const int bc16 = (t & 7) * 16;
        int garow = row0 + arow; if (garow >= NN) garow = NN - 1;
        const __half* Ap = g_h1h + (size_t)garow * NHID;
        const __half* Bp = g_wmlh + bc16;

        const int NIT = NHID / 32;   // 8
        cp_async16(&hA[0][arow][ac16],     Ap + ac16);
        cp_async16(&hA[0][arow][ac16 + 8], Ap + ac16 + 8);
        cp_async16(&hB[0][brow][bc16],     Bp + (size_t)brow * 128);
        cp_async16(&hB[0][brow][bc16 + 8], Bp + (size_t)brow * 128 + 8);
        cp_commit();

        for (int i = 0; i < NIT; i++) {
            if (i + 1 < NIT) {
                int k1 = (i + 1) * 32;
                int nb = (i + 1) & 1;
                cp_async16(&hA[nb][arow][ac16],     Ap + k1 + ac16);
                cp_async16(&hA[nb][arow][ac16 + 8], Ap + k1 + ac16 + 8);
                cp_async16(&hB[nb][brow][bc16],     Bp + (size_t)(k1 + brow) * 128);
                cp_async16(&hB[nb][brow][bc16 + 8], Bp + (size_t)(k1 + brow) * 128 + 8);
                cp_commit();
                cp_wait1();
            } else {
                cp_wait0();
            }
            __syncthreads();
            int cb = i & 1;
#pragma unroll
            for (int kk = 0; kk < 32; kk += 16) {
                wmma::fragment<wmma::matrix_a, 16, 16, 16, __half, wmma::row_major> af[4];
                wmma::fragment<wmma::matrix_b, 16, 16, 16, __half, wmma::row_major> bf[2];
#pragma unroll
                for (int ii = 0; ii < 4; ii++)
                    wmma::load_matrix_sync(af[ii], &hA[cb][wr * 64 + ii * 16][kk], 40);
#pragma unroll
                for (int j = 0; j < 2; j++)
                    wmma::load_matrix_sync(bf[j], &hB[cb][kk][wc * 32 + j * 16], 136);
#pragma unroll
                for (int ii = 0; ii < 4; ii++)
#pragma unroll
                    for (int j = 0; j < 2; j++)
                        wmma::mma_sync(acc[ii][j], af[ii], bf[j], acc[ii][j]);
            }
            __syncthreads();
        }
    }

    // ---- phase z ----
    if (wc >= 2) {
        // publish lv columns (cols 64..127 -> local 0..63) as fp32
#pragma unroll
        for (int i = 0; i < 4; i++)
#pragma unroll
            for (int j = 0; j < 2; j++)
                wmma::store_matrix_sync(lv_s + (wr * 64 + i * 16) * 68 + (wc - 2) * 32 + j * 16,
                                        acc[i][j], 68, wmma::mem_row_major);
    }
    __syncthreads();
    if (wc < 2) {
        float* stage = stg + wid * 320;
#pragma unroll
        for (int i = 0; i < 4; i++)
#pragma unroll
            for (int j = 0; j < 2; j++) {
                wmma::store_matrix_sync(stage, acc[i][j], 20, wmma::mem_row_major);
                __syncwarp();
                const float* sp = stage + rr * 20 + cc;
                int row = wr * 64 + i * 16 + rr;       // 0..127
                int col = wc * 32 + j * 16 + cc;       // 0..63
                int ge = row0 + row; if (ge >= NN) ge = NN - 1;
                float4 e0 = *(const float4*)(eps + (size_t)ge * NCODE + col);
                float4 e1 = *(const float4*)(eps + (size_t)ge * NCODE + col + 4);
                float4 l0 = *(const float4*)(lv_s + row * 68 + col);
                float4 l1 = *(const float4*)(lv_s + row * 68 + col + 4);
                float4 bm0 = *(const float4*)(bmu + col);
                float4 bm1 = *(const float4*)(bmu + col + 4);
                float4 bl0 = *(const float4*)(blv + col);
                float4 bl1 = *(const float4*)(blv + col + 4);
                float z0 = (sp[0] + bm0.x) + e0.x * expf(l0.x + bl0.x);
                float z1 = (sp[1] + bm0.y) + e0.y * expf(l0.y + bl0.y);
                float z2 = (sp[2] + bm0.z) + e0.z * expf(l0.z + bl0.z);
                float z3 = (sp[3] + bm0.w) + e0.w * expf(l0.w + bl0.w);
                float z4 = (sp[4] + bm1.x) + e1.x * expf(l1.x + bl1.x);
                float z5 = (sp[5] + bm1.y) + e1.y * expf(l1.y + bl1.y);
                float z6 = (sp[6] + bm1.z) + e1.z * expf(l1.z + bl1.z);
                float z7 = (sp[7] + bm1.w) + e1.w * expf(l1.w + bl1.w);
                *(uint4*)(z_s + row * 72 + col) =
                    make_uint4(h2u(__floats2half2_rn(z0, z1)), h2u(__floats2half2_rn(z2, z3)),
                               h2u(__floats2half2_rn(z4, z5)), h2u(__floats2half2_rn(z6, z7)));
                __syncwarp();
            }
    }
    __syncthreads();

    // ---- phase 2: x1 = relu(z @ Wdec + bdec), K=64, N=256 in two halves ----
    for (int col0 = 0; col0 < NHID; col0 += 128) {
        // load Wdec[0..63][col0..col0+127] -> bB [64][136]
        {
            const __half* wp = g_wdech + (size_t)(t >> 2) * NHID + col0 + (t & 3) * 32;
            __half* bp = bB + (t >> 2) * 136 + (t & 3) * 32;
            *(uint4*)(bp)      = *(const uint4*)(wp);
            *(uint4*)(bp + 8)  = *(const uint4*)(wp + 8);
            *(uint4*)(bp + 16) = *(const uint4*)(wp + 16);
            *(uint4*)(bp + 24) = *(const uint4*)(wp + 24);
        }
        __syncthreads();

        wmma::fragment<wmma::accumulator, 16, 16, 16, float> acc2[4][2];
#pragma unroll
        for (int i = 0; i < 4; i++)
#pragma unroll
            for (int j = 0; j < 2; j++) wmma::fill_fragment(acc2[i][j], 0.0f);

#pragma unroll
        for (int kk = 0; kk < NCODE; kk += 16) {
            wmma::fragment<wmma::matrix_a, 16, 16, 16, __half, wmma::row_major> af[4];
            wmma::fragment<wmma::matrix_b, 16, 16, 16, __half, wmma::row_major> bf[2];
#pragma unroll
            for (int i = 0; i < 4; i++)
                wmma::load_matrix_sync(af[i], z_s + (wr * 64 + i * 16) * 72 + kk, 72);
#pragma unroll
            for (int j = 0; j < 2; j++)
                wmma::load_matrix_sync(bf[j], bB + kk * 136 + wc * 32 + j * 16, 136);
#pragma unroll
            for (int i = 0; i < 4; i++)
#pragma unroll
                for (int j = 0; j < 2; j++)
                    wmma::mma_sync(acc2[i][j], af[i], bf[j], acc2[i][j]);
        }

        // epilogue: + bdec, relu, fp16 -> g_x1h
        float* stage = stg + wid * 320;
#pragma unroll
        for (int i = 0; i < 4; i++)
#pragma unroll
            for (int j = 0; j < 2; j++) {
                wmma::store_matrix_sync(stage, acc2[i][j], 20, wmma::mem_row_major);
                __syncwarp();
                const float* sp = stage + rr * 20 + cc;
                int gr = row0 + wr * 64 + i * 16 + rr;
                int gc = col0 + wc * 32 + j * 16 + cc;
                float4 bd0 = *(const float4*)(bdec + gc);
                float4 bd1 = *(const float4*)(bdec + gc + 4);
                float v0 = fmaxf(sp[0] + bd0.x, 0.f), v1 = fmaxf(sp[1] + bd0.y, 0.f);
                float v2 = fmaxf(sp[2] + bd0.z, 0.f), v3 = fmaxf(sp[3] + bd0.w, 0.f);
                float v4 = fmaxf(sp[4] + bd1.x, 0.f), v5 = fmaxf(sp[5] + bd1.y, 0.f);
                float v6 = fmaxf(sp[6] + bd1.z, 0.f), v7 = fmaxf(sp[7] + bd1.w, 0.f);
                *(uint4*)(g_x1h + (size_t)gr * NHID + gc) =
                    make_uint4(h2u(__floats2half2_rn(v0, v1)), h2u(__floats2half2_rn(v2, v3)),
                               h2u(__floats2half2_rn(v4, v5)), h2u(__floats2half2_rn(v6, v7)));
                __syncwarp();
            }
        __syncthreads();
    }
}

// =========================================================================
// out gemm (fp16 HMMA, cp.async double-buffered): g_support2 = [x1;h1] @ W2
// M=NP, K=512, N=64 (pre-padded). 8 warps (4x2), warp 32x32. BK=32.
// =========================================================================
__global__ __launch_bounds__(256) void out_tc() {
    __shared__ __half As[2][128][40];
    __shared__ __half Bs[2][32][72];
    const int t   = threadIdx.x;
    const int wid = t >> 5;
    const int wr  = wid >> 1;     // 0..3
    const int wc  = wid & 1;      // 0..1
    const int row0 = blockIdx.x * 128;

    wmma::fragment<wmma::accumulator, 16, 16, 16, float> acc[2][2];
#pragma unroll
    for (int i = 0; i < 2; i++)
#pragma unroll
        for (int j = 0; j < 2; j++) wmma::fill_fragment(acc[i][j], 0.0f);

    const int arow = t >> 1;
    const int ac16 = (t & 1) * 16;
    const int brow = t >> 3;          // 0..31
    const int bc8  = (t & 7) * 8;     // 0..56
    int garow = row0 + arow; if (garow >= NN) garow = NN - 1;
    const __half* Ap1 = g_x1h + (size_t)garow * NHID;
    const __half* Ap2 = g_h1h + (size_t)garow * NHID;

    const int NIT = 2 * NHID / 32;   // 16
    {
        const __half* ap = Ap1 + ac16;   // k0 = 0 < NHID
        cp_async16(&As[0][arow][ac16],     ap);
        cp_async16(&As[0][arow][ac16 + 8], ap + 8);
        cp_async16(&Bs[0][brow][bc8], g_w2h + (size_t)brow * 64 + bc8);
    }
    cp_commit();

    for (int i = 0; i < NIT; i++) {
        if (i + 1 < NIT) {
            int k1 = (i + 1) * 32;
            int nb = (i + 1) & 1;
            const __half* ap = (k1 < NHID) ? (Ap1 + k1 + ac16)
                                           : (Ap2 + (k1 - NHID) + ac16);
            cp_async16(&As[nb][arow][ac16],     ap);
            cp_async16(&As[nb][arow][ac16 + 8], ap + 8);
            cp_async16(&Bs[nb][brow][bc8], g_w2h + (size_t)(k1 + brow) * 64 + bc8);
            cp_commit();
            cp_wait1();
        } else {
            cp_wait0();
        }
        __syncthreads();
        int cb = i & 1;
#pragma unroll
        for (int kk = 0; kk < 32; kk += 16) {
            wmma::fragment<wmma::matrix_a, 16, 16, 16, __half, wmma::row_major> af[2];
            wmma::fragment<wmma::matrix_b, 16, 16, 16, __half, wmma::row_major> bf[2];
#pragma unroll
            for (int ii = 0; ii < 2; ii++)
                wmma::load_matrix_sync(af[ii], &As[cb][wr * 32 + ii * 16][kk], 40);
#pragma unroll
            for (int j = 0; j < 2; j++)
                wmma::load_matrix_sync(bf[j], &Bs[cb][kk][wc * 32 + j * 16], 72);
#pragma unroll
            for (int ii = 0; ii < 2; ii++)
#pragma unroll
                for (int j = 0; j < 2; j++)
                    wmma::mma_sync(acc[ii][j], af[ii], bf[j], acc[ii][j]);
        }
        __syncthreads();
    }
#pragma unroll
    for (int i = 0; i < 2; i++)
#pragma unroll
        for (int j = 0; j < 2; j++) {
            int r = row0 + wr * 32 + i * 16;
            int c = wc * 32 + j * 16;
            wmma::store_matrix_sync(g_support2 + (size_t)r * 64 + c, acc[i][j],
                                    64, wmma::mem_row_major);
        }
}

// ---------------- spmm1 + bias + relu (fp16 gather -> fp16 h1) -----------
__global__ void spmm_relu_kernel(const float* __restrict__ b1) {
    int warp = (blockIdx.x * blockDim.x + threadIdx.x) >> 5;
    int lane = threadIdx.x & 31;
    if (warp >= NN) return;
    int beg = g_rowptr[warp];
    int end = g_rowptr[warp + 1];
    float acc[8] = {0, 0, 0, 0, 0, 0, 0, 0};
    const int co = lane * 8;
    int e = beg;
    for (; e + 4 <= end; e += 4) {
        int   s0 = g_esrc[e],   s1 = g_esrc[e + 1], s2 = g_esrc[e + 2], s3 = g_esrc[e + 3];
        float w0 = g_ew[e],     w1 = g_ew[e + 1],   w2 = g_ew[e + 2],   w3 = g_ew[e + 3];
        uint4 u0 = *(const uint4*)(g_support1h + (size_t)s0 * NHID + co);
        uint4 u1 = *(const uint4*)(g_support1h + (size_t)s1 * NHID + co);
        uint4 u2 = *(const uint4*)(g_support1h + (size_t)s2 * NHID + co);
        uint4 u3 = *(const uint4*)(g_support1h + (size_t)s3 * NHID + co);
        __half2* h0 = (__half2*)&u0;
        __half2* h1 = (__half2*)&u1;
        __half2* h2 = (__half2*)&u2;
        __half2* h3 = (__half2*)&u3;
#pragma unroll
        for (int q = 0; q < 4; q++) {
            float2 f0 = __half22float2(h0[q]);
            float2 f1 = __half22float2(h1[q]);
            float2 f2 = __half22float2(h2[q]);
            float2 f3 = __half22float2(h3[q]);
            acc[2 * q]     += w0 * f0.x + w1 * f1.x + w2 * f2.x + w3 * f3.x;
            acc[2 * q + 1] += w0 * f0.y + w1 * f1.y + w2 * f2.y + w3 * f3.y;
        }
    }
    for (; e < end; e++) {
        int s = g_esrc[e];
        float w = g_ew[e];
        uint4 u = *(const uint4*)(g_support1h + (size_t)s * NHID + co);
        __half2* h = (__half2*)&u;
#pragma unroll
        for (int q = 0; q < 4; q++) {
            float2 f = __half22float2(h[q]);
            acc[2 * q]     += w * f.x;
            acc[2 * q + 1] += w * f.y;
        }
    }
    float4 bb0 = *(const float4*)(b1 + co);
    float4 bb1 = *(const float4*)(b1 + co + 4);
    float o[8];
    o[0] = fmaxf(acc[0] + bb0.x, 0.f); o[1] = fmaxf(acc[1] + bb0.y, 0.f);
    o[2] = fmaxf(acc[2] + bb0.z, 0.f); o[3] = fmaxf(acc[3] + bb0.w, 0.f);
    o[4] = fmaxf(acc[4] + bb1.x, 0.f); o[5] = fmaxf(acc[5] + bb1.y, 0.f);
    o[6] = fmaxf(acc[6] + bb1.z, 0.f); o[7] = fmaxf(acc[7] + bb1.w, 0.f);
    uint4 u = make_uint4(h2u(__floats2half2_rn(o[0], o[1])),
                         h2u(__floats2half2_rn(o[2], o[3])),
                         h2u(__floats2half2_rn(o[4], o[5])),
                         h2u(__floats2half2_rn(o[6], o[7])));
    *(uint4*)(g_h1h + (size_t)warp * NHID + co) = u;
}

// ---------------- spmm2 + b2 + log_softmax -> out ----------------
__global__ void spmm_softmax_kernel(const float* __restrict__ b2,
                                    float* __restrict__ out) {
    int warp = (blockIdx.x * blockDim.x + threadIdx.x) >> 5;
    int lane = threadIdx.x & 31;
    if (warp >= NN) return;
    int beg = g_rowptr[warp];
    int end = g_rowptr[warp + 1];
    bool active = lane < 10;
    float4 acc = make_float4(0, 0, 0, 0);
    const float4* S = (const float4*)g_support2;   // stride 16 float4 / row
    for (int e = beg; e < end; e++) {
        int s = g_esrc[e];
        float w = g_ew[e];
        if (active) {
            float4 v = __ldg(S + (size_t)s * 16 + lane);
            acc.x += w * v.x; acc.y += w * v.y; acc.z += w * v.z; acc.w += w * v.w;
        }
    }
    float4 v = make_float4(-INFINITY, -INFINITY, -INFINITY, -INFINITY);
    if (active) {
        float4 b = ((const float4*)b2)[lane];
        v.x = acc.x + b.x; v.y = acc.y + b.y; v.z = acc.z + b.z; v.w = acc.w + b.w;
    }
    float m = fmaxf(fmaxf(v.x, v.y), fmaxf(v.z, v.w));
#pragma unroll
    for (int off = 16; off > 0; off >>= 1)
        m = fmaxf(m, __shfl_xor_sync(0xFFFFFFFFu, m, off));
    float s = active ? (expf(v.x - m) + expf(v.y - m) + expf(v.z - m) + expf(v.w - m)) : 0.0f;
#pragma unroll
    for (int off = 16; off > 0; off >>= 1)
        s += __shfl_xor_sync(0xFFFFFFFFu, s, off);
    float lse = m + logf(s);
    if (active) {
        float4 o;
        o.x = v.x - lse; o.y = v.y - lse; o.z = v.z - lse; o.w = v.w - lse;
        ((float4*)out)[(size_t)warp * 10 + lane] = o;
    }
}

// ---------------- launch ----------------
extern "C" void kernel_launch(void* const* d_in, const int* in_sizes, int n_in,
                              void* d_out, int out_size) {
    const float* x        = (const float*)d_in[0];
    const int*   edge_src = (const int*)  d_in[1];
    const int*   edge_dst = (const int*)  d_in[2];
    const float* edge_w   = (const float*)d_in[3];
    const float* eps      = (const float*)d_in[4];
    const float* W1       = (const float*)d_in[5];
    const float* b1       = (const float*)d_in[6];
    const float* W_mu     = (const float*)d_in[7];
    const float* b_mu     = (const float*)d_in[8];
    const float* W_lv     = (const float*)d_in[9];
    const float* b_lv     = (const float*)d_in[10];
    const float* W_dec    = (const float*)d_in[11];
    const float* b_dec    = (const float*)d_in[12];
    const float* W2       = (const float*)d_in[13];
    const float* b2       = (const float*)d_in[14];
    float* out = (float*)d_out;

    static bool attr_set = false;
    if (!attr_set) {
        cudaFuncSetAttribute(zdec_tc, cudaFuncAttributeMaxDynamicSharedMemorySize, 65536);
        attr_set = true;
    }

    // zero counts via async memset
    void* cnt_ptr = nullptr;
    cudaGetSymbolAddress(&cnt_ptr, g_cnt);
    cudaMemsetAsync(cnt_ptr, 0, NN * sizeof(int));

    // kernel index:  0      1      2     3 (ncu window)  4     5
    cvt_w_kernel<<<(NFEAT * NHID + 255) / 256, 256>>>(W1, W_mu, W_lv, W_dec, W2);  // 0
    cvt_x_kernel<<<((size_t)NN * NFEAT / 8 + 255) / 256, 256>>>(x);                // 1
    hist_kernel<<<(EE + 255) / 256, 256>>>(edge_dst);                              // 2
    gemm1_tc<<<dim3(NHID / 128, NP / 128), 256>>>();                               // 3
    scan_kernel<<<1, 1024>>>();                                                    // 4
    scatter_kernel<<<(EE + 255) / 256, 256>>>(edge_src, edge_dst, edge_w);         // 5

    // h1(fp16) = relu(spmm + b1)
    spmm_relu_kernel<<<(NN * 32 + 255) / 256, 256>>>(b1);

    // fused: tmp -> z -> x1
    zdec_tc<<<NP / 128, 256, 65536>>>(b_mu, b_lv, eps, b_dec);

    // support2 = [x1; h1] @ W2
    out_tc<<<NP / 128, 256>>>();

    // out = log_softmax(spmm + b2)
    spmm_softmax_kernel<<<(NN * 32 + 255) / 256, 256>>>(b2, out);
}

// round 13
// speedup vs baseline: 1.6227x; 1.2419x over previous
#include <cuda_runtime.h>
#include <mma.h>
#include <math.h>
#include <stdint.h>
#include <cuda_fp16.h>

using namespace nvcuda;

#define NN      50000
#define NP      50048            // NN padded to multiple of 128
#define EE      800000
#define NFEAT   512
#define NHID    256
#define NCODE   64
#define NCLASS  40

// ---------------- device scratch (static, allocation-free) ----------------
__device__ __align__(16) __half g_xh  [(size_t)NN * NFEAT];     // fp16(x)
__device__ __align__(16) __half g_w1h [NFEAT * NHID];           // fp16(W1)
__device__ __align__(16) __half g_wmlh[NHID * 128];             // fp16([Wmu|Wlv])
__device__ __align__(16) __half g_wdech[NCODE * NHID];          // fp16(Wdec)
__device__ __align__(16) __half g_w2h [2 * NHID * 64];          // fp16(W2) padded cols
__device__ __align__(16) __half g_support1h[(size_t)NP * NHID]; // x @ W1 (fp16)
__device__ __align__(16) __half g_h1h[(size_t)NP * NHID];       // relu(spmm + b1) fp16
__device__ __align__(16) __half g_x1h[(size_t)NP * NHID];       // relu(z @ Wdec + bdec) fp16
__device__ __align__(16) __half g_support2h[(size_t)NP * 64];   // concat @ W2 fp16 (padded)
__device__ int   g_cnt   [NN];
__device__ int   g_rowptr[NN + 1];
__device__ int   g_cursor[NN];
__device__ int   g_esrc[EE];
__device__ float g_ew  [EE];

__device__ __forceinline__ unsigned h2u(__half2 h) {
    return *(unsigned*)&h;
}

__device__ __forceinline__ void cp_async16(void* smem, const void* gmem) {
    unsigned int s = (unsigned int)__cvta_generic_to_shared(smem);
    asm volatile("cp.async.cg.shared.global [%0], [%1], 16;" :: "r"(s), "l"(gmem));
}
__device__ __forceinline__ void cp_commit() {
    asm volatile("cp.async.commit_group;");
}
__device__ __forceinline__ void cp_wait1() {
    asm volatile("cp.async.wait_group 1;");
}
__device__ __forceinline__ void cp_wait0() {
    asm volatile("cp.async.wait_group 0;");
}

// ---------------- fp16 conversion kernels ----------------
__global__ void cvt_w_kernel(const float* __restrict__ W1,
                             const float* __restrict__ Wmu,
                             const float* __restrict__ Wlv,
                             const float* __restrict__ Wdec,
                             const float* __restrict__ W2) {
    int i = blockIdx.x * blockDim.x + threadIdx.x;
    if (i < NFEAT * NHID) g_w1h[i] = __float2half_rn(W1[i]);
    if (i < NHID * 128) {
        int k = i >> 7, j = i & 127;
        float v = (j < 64) ? Wmu[k * NCODE + j] : Wlv[k * NCODE + (j - 64)];
        g_wmlh[i] = __float2half_rn(v);
    }
    if (i < NCODE * NHID) g_wdech[i] = __float2half_rn(Wdec[i]);
    if (i < 2 * NHID * 64) {
        int k = i >> 6, j = i & 63;
        g_w2h[i] = __float2half_rn(j < NCLASS ? W2[k * NCLASS + j] : 0.0f);
    }
}

__global__ void cvt_x_kernel(const float* __restrict__ x) {
    size_t i = (size_t)blockIdx.x * blockDim.x + threadIdx.x;   // over NN*NFEAT/8
    if (i >= (size_t)NN * NFEAT / 8) return;
    const float4* p = (const float4*)x + i * 2;
    float4 a = p[0], b = p[1];
    uint4 u = make_uint4(h2u(__floats2half2_rn(a.x, a.y)), h2u(__floats2half2_rn(a.z, a.w)),
                         h2u(__floats2half2_rn(b.x, b.y)), h2u(__floats2half2_rn(b.z, b.w)));
    ((uint4*)g_xh)[i] = u;
}

// ---------------- CSR build ----------------
__global__ void hist_kernel(const int* __restrict__ dst) {
    int e = blockIdx.x * blockDim.x + threadIdx.x;
    if (e < EE) atomicAdd(&g_cnt[dst[e]], 1);
}

__global__ __launch_bounds__(1024) void scan_kernel() {
    __shared__ int sums[1024];
    const int T = 1024;
    const int IT = (NN + T - 1) / T;
    int t = threadIdx.x;
    int base = t * IT;
    int s = 0;
    for (int i = 0; i < IT; i++) {
        int idx = base + i;
        if (idx < NN) s += g_cnt[idx];
    }
    sums[t] = s;
    __syncthreads();
    for (int off = 1; off < T; off <<= 1) {
        int v = (t >= off) ? sums[t - off] : 0;
        __syncthreads();
        sums[t] += v;
        __syncthreads();
    }
    int run = sums[t] - s;
    for (int i = 0; i < IT; i++) {
        int idx = base + i;
        if (idx < NN) {
            g_rowptr[idx] = run;
            g_cursor[idx] = run;
            run += g_cnt[idx];
        }
    }
    if (t == T - 1) g_rowptr[NN] = sums[T - 1];
}

__global__ void scatter_kernel(const int* __restrict__ src,
                               const int* __restrict__ dst,
                               const float* __restrict__ w) {
    int e = blockIdx.x * blockDim.x + threadIdx.x;
    if (e < EE) {
        int d = dst[e];
        int p = atomicAdd(&g_cursor[d], 1);
        g_esrc[p] = src[e];
        g_ew[p]   = w[e];
    }
}

// =========================================================================
// GEMM1 (fp16 HMMA, cp.async double-buffered): g_support1h = fp16(x @ W1)
// M=NP, K=512, N=256. BM=128, BN=128, BK=32, 8 warps (2x4), warp 64x32.
// =========================================================================
__global__ __launch_bounds__(256) void gemm1_tc() {
    __shared__ __half As[2][128][40];
    __shared__ __half Bs[2][32][136];
    const int t   = threadIdx.x;
    const int wid = t >> 5;
    const int wr  = wid >> 2;     // 0..1
    const int wc  = wid & 3;      // 0..3
    const int row0 = blockIdx.y * 128;
    const int col0 = blockIdx.x * 128;

    wmma::fragment<wmma::accumulator, 16, 16, 16, float> acc[4][2];
#pragma unroll
    for (int i = 0; i < 4; i++)
#pragma unroll
        for (int j = 0; j < 2; j++) wmma::fill_fragment(acc[i][j], 0.0f);

    const int arow = t >> 1;          // 0..127
    const int ac16 = (t & 1) * 16;    // 0/16
    const int brow = t >> 3;          // 0..31
    const int bc16 = (t & 7) * 16;    // 0..112
    int garow = row0 + arow; if (garow >= NN) garow = NN - 1;
    const __half* Ap = g_xh + (size_t)garow * NFEAT;
    const __half* Bp = g_w1h + col0 + bc16;

    const int NIT = NFEAT / 32;   // 16
    cp_async16(&As[0][arow][ac16],     Ap + ac16);
    cp_async16(&As[0][arow][ac16 + 8], Ap + ac16 + 8);
    cp_async16(&Bs[0][brow][bc16],     Bp + (size_t)brow * NHID);
    cp_async16(&Bs[0][brow][bc16 + 8], Bp + (size_t)brow * NHID + 8);
    cp_commit();

    for (int i = 0; i < NIT; i++) {
        if (i + 1 < NIT) {
            int k1 = (i + 1) * 32;
            int nb = (i + 1) & 1;
            cp_async16(&As[nb][arow][ac16],     Ap + k1 + ac16);
            cp_async16(&As[nb][arow][ac16 + 8], Ap + k1 + ac16 + 8);
            cp_async16(&Bs[nb][brow][bc16],     Bp + (size_t)(k1 + brow) * NHID);
            cp_async16(&Bs[nb][brow][bc16 + 8], Bp + (size_t)(k1 + brow) * NHID + 8);
            cp_commit();
            cp_wait1();
        } else {
            cp_wait0();
        }
        __syncthreads();
        int cb = i & 1;
#pragma unroll
        for (int kk = 0; kk < 32; kk += 16) {
            wmma::fragment<wmma::matrix_a, 16, 16, 16, __half, wmma::row_major> af[4];
            wmma::fragment<wmma::matrix_b, 16, 16, 16, __half, wmma::row_major> bf[2];
#pragma unroll
            for (int ii = 0; ii < 4; ii++)
                wmma::load_matrix_sync(af[ii], &As[cb][wr * 64 + ii * 16][kk], 40);
#pragma unroll
            for (int j = 0; j < 2; j++)
                wmma::load_matrix_sync(bf[j], &Bs[cb][kk][wc * 32 + j * 16], 136);
#pragma unroll
            for (int ii = 0; ii < 4; ii++)
#pragma unroll
                for (int j = 0; j < 2; j++)
                    wmma::mma_sync(acc[ii][j], af[ii], bf[j], acc[ii][j]);
        }
        __syncthreads();
    }

    float* stage = (float*)&As[0][0][0] + wid * 320;
    const int L = t & 31;
    const int rr = L >> 1;
    const int cc = (L & 1) * 8;
#pragma unroll
    for (int i = 0; i < 4; i++)
#pragma unroll
        for (int j = 0; j < 2; j++) {
            wmma::store_matrix_sync(stage, acc[i][j], 20, wmma::mem_row_major);
            __syncwarp();
            const float* sp = stage + rr * 20 + cc;
            __half2 h0 = __floats2half2_rn(sp[0], sp[1]);
            __half2 h1 = __floats2half2_rn(sp[2], sp[3]);
            __half2 h2 = __floats2half2_rn(sp[4], sp[5]);
            __half2 h3 = __floats2half2_rn(sp[6], sp[7]);
            int gr = row0 + wr * 64 + i * 16 + rr;
            int gc = col0 + wc * 32 + j * 16 + cc;
            *(uint4*)(g_support1h + (size_t)gr * NHID + gc) =
                make_uint4(h2u(h0), h2u(h1), h2u(h2), h2u(h3));
            __syncwarp();
        }
}

// =========================================================================
// zdec fused: phase1 tmp = h1 @ [Wmu|Wlv] (regs);
// phase z: z = (mu+bmu) + eps*exp(lv+blv) via smem exchange (fp16 tile);
// phase2: x1 = relu(z @ Wdec + bdec) -> g_x1h.
// =========================================================================
__global__ __launch_bounds__(256) void zdec_tc(const float* __restrict__ bmu,
                                               const float* __restrict__ blv,
                                               const float* __restrict__ eps,
                                               const float* __restrict__ bdec) {
    extern __shared__ char arena[];
    __half (*hA)[128][40]  = (__half (*)[128][40])arena;            // 20480 B
    __half (*hB)[32][136]  = (__half (*)[32][136])(arena + 20480);  // 17408 B
    float*  lv_s  = (float*)arena;                   // [128][68]  34816 B
    __half* z_s   = (__half*)(arena + 34816);        // [128][72]  18432 B
    float*  stg   = (float*)(arena + 53248);         // 8 * 320 floats
    __half* bB    = (__half*)arena;                  // [64][136]  17408 B (phase2)

    const int t   = threadIdx.x;
    const int wid = t >> 5;
    const int wr  = wid >> 2;     // 0..1
    const int wc  = wid & 3;      // 0..3
    const int row0 = blockIdx.x * 128;
    const int L  = t & 31;
    const int rr = L >> 1;
    const int cc = (L & 1) * 8;

    wmma::fragment<wmma::accumulator, 16, 16, 16, float> acc[4][2];
#pragma unroll
    for (int i = 0; i < 4; i++)
#pragma unroll
        for (int j = 0; j < 2; j++) wmma::fill_fragment(acc[i][j], 0.0f);

    // ---- phase 1: tmp = h1 @ [Wmu|Wlv], K=256, N=128 ----
    {
        const int arow = t >> 1;
        const int ac16 = (t & 1) * 16;
        const int brow = t >> 3;
        const int bc16 = (t & 7) * 16;
        int garow = row0 + arow; if (garow >= NN) garow = NN - 1;
        const __half* Ap = g_h1h + (size_t)garow * NHID;
        const __half* Bp = g_wmlh + bc16;

        const int NIT = NHID / 32;   // 8
        cp_async16(&hA[0][arow][ac16],     Ap + ac16);
        cp_async16(&hA[0][arow][ac16 + 8], Ap + ac16 + 8);
        cp_async16(&hB[0][brow][bc16],     Bp + (size_t)brow * 128);
        cp_async16(&hB[0][brow][bc16 + 8], Bp + (size_t)brow * 128 + 8);
        cp_commit();

        for (int i = 0; i < NIT; i++) {
            if (i + 1 < NIT) {
                int k1 = (i + 1) * 32;
                int nb = (i + 1) & 1;
                cp_async16(&hA[nb][arow][ac16],     Ap + k1 + ac16);
                cp_async16(&hA[nb][arow][ac16 + 8], Ap + k1 + ac16 + 8);
                cp_async16(&hB[nb][brow][bc16],     Bp + (size_t)(k1 + brow) * 128);
                cp_async16(&hB[nb][brow][bc16 + 8], Bp + (size_t)(k1 + brow) * 128 + 8);
                cp_commit();
                cp_wait1();
            } else {
                cp_wait0();
            }
            __syncthreads();
            int cb = i & 1;
#pragma unroll
            for (int kk = 0; kk < 32; kk += 16) {
                wmma::fragment<wmma::matrix_a, 16, 16, 16, __half, wmma::row_major> af[4];
                wmma::fragment<wmma::matrix_b, 16, 16, 16, __half, wmma::row_major> bf[2];
#pragma unroll
                for (int ii = 0; ii < 4; ii++)
                    wmma::load_matrix_sync(af[ii], &hA[cb][wr * 64 + ii * 16][kk], 40);
#pragma unroll
                for (int j = 0; j < 2; j++)
                    wmma::load_matrix_sync(bf[j], &hB[cb][kk][wc * 32 + j * 16], 136);
#pragma unroll
                for (int ii = 0; ii < 4; ii++)
#pragma unroll
                    for (int j = 0; j < 2; j++)
                        wmma::mma_sync(acc[ii][j], af[ii], bf[j], acc[ii][j]);
            }
            __syncthreads();
        }
    }

    // ---- phase z ----
    if (wc >= 2) {
#pragma unroll
        for (int i = 0; i < 4; i++)
#pragma unroll
            for (int j = 0; j < 2; j++)
                wmma::store_matrix_sync(lv_s + (wr * 64 + i * 16) * 68 + (wc - 2) * 32 + j * 16,
                                        acc[i][j], 68, wmma::mem_row_major);
    }
    __syncthreads();
    if (wc < 2) {
        float* stage = stg + wid * 320;
#pragma unroll
        for (int i = 0; i < 4; i++)
#pragma unroll
            for (int j = 0; j < 2; j++) {
                wmma::store_matrix_sync(stage, acc[i][j], 20, wmma::mem_row_major);
                __syncwarp();
                const float* sp = stage + rr * 20 + cc;
                int row = wr * 64 + i * 16 + rr;
                int col = wc * 32 + j * 16 + cc;
                int ge = row0 + row; if (ge >= NN) ge = NN - 1;
                float4 e0 = *(const float4*)(eps + (size_t)ge * NCODE + col);
                float4 e1 = *(const float4*)(eps + (size_t)ge * NCODE + col + 4);
                float4 l0 = *(const float4*)(lv_s + row * 68 + col);
                float4 l1 = *(const float4*)(lv_s + row * 68 + col + 4);
                float4 bm0 = *(const float4*)(bmu + col);
                float4 bm1 = *(const float4*)(bmu + col + 4);
                float4 bl0 = *(const float4*)(blv + col);
                float4 bl1 = *(const float4*)(blv + col + 4);
                float z0 = (sp[0] + bm0.x) + e0.x * expf(l0.x + bl0.x);
                float z1 = (sp[1] + bm0.y) + e0.y * expf(l0.y + bl0.y);
                float z2 = (sp[2] + bm0.z) + e0.z * expf(l0.z + bl0.z);
                float z3 = (sp[3] + bm0.w) + e0.w * expf(l0.w + bl0.w);
                float z4 = (sp[4] + bm1.x) + e1.x * expf(l1.x + bl1.x);
                float z5 = (sp[5] + bm1.y) + e1.y * expf(l1.y + bl1.y);
                float z6 = (sp[6] + bm1.z) + e1.z * expf(l1.z + bl1.z);
                float z7 = (sp[7] + bm1.w) + e1.w * expf(l1.w + bl1.w);
                *(uint4*)(z_s + row * 72 + col) =
                    make_uint4(h2u(__floats2half2_rn(z0, z1)), h2u(__floats2half2_rn(z2, z3)),
                               h2u(__floats2half2_rn(z4, z5)), h2u(__floats2half2_rn(z6, z7)));
                __syncwarp();
            }
    }
    __syncthreads();

    // ---- phase 2: x1 = relu(z @ Wdec + bdec), K=64, N=256 in two halves ----
    for (int col0 = 0; col0 < NHID; col0 += 128) {
        {
            const __half* wp = g_wdech + (size_t)(t >> 2) * NHID + col0 + (t & 3) * 32;
            __half* bp = bB + (t >> 2) * 136 + (t & 3) * 32;
            *(uint4*)(bp)      = *(const uint4*)(wp);
            *(uint4*)(bp + 8)  = *(const uint4*)(wp + 8);
            *(uint4*)(bp + 16) = *(const uint4*)(wp + 16);
            *(uint4*)(bp + 24) = *(const uint4*)(wp + 24);
        }
        __syncthreads();

        wmma::fragment<wmma::accumulator, 16, 16, 16, float> acc2[4][2];
#pragma unroll
        for (int i = 0; i < 4; i++)
#pragma unroll
            for (int j = 0; j < 2; j++) wmma::fill_fragment(acc2[i][j], 0.0f);

#pragma unroll
        for (int kk = 0; kk < NCODE; kk += 16) {
            wmma::fragment<wmma::matrix_a, 16, 16, 16, __half, wmma::row_major> af[4];
            wmma::fragment<wmma::matrix_b, 16, 16, 16, __half, wmma::row_major> bf[2];
#pragma unroll
            for (int i = 0; i < 4; i++)
                wmma::load_matrix_sync(af[i], z_s + (wr * 64 + i * 16) * 72 + kk, 72);
#pragma unroll
            for (int j = 0; j < 2; j++)
                wmma::load_matrix_sync(bf[j], bB + kk * 136 + wc * 32 + j * 16, 136);
#pragma unroll
            for (int i = 0; i < 4; i++)
#pragma unroll
                for (int j = 0; j < 2; j++)
                    wmma::mma_sync(acc2[i][j], af[i], bf[j], acc2[i][j]);
        }

        float* stage = stg + wid * 320;
#pragma unroll
        for (int i = 0; i < 4; i++)
#pragma unroll
            for (int j = 0; j < 2; j++) {
                wmma::store_matrix_sync(stage, acc2[i][j], 20, wmma::mem_row_major);
                __syncwarp();
                const float* sp = stage + rr * 20 + cc;
                int gr = row0 + wr * 64 + i * 16 + rr;
                int gc = col0 + wc * 32 + j * 16 + cc;
                float4 bd0 = *(const float4*)(bdec + gc);
                float4 bd1 = *(const float4*)(bdec + gc + 4);
                float v0 = fmaxf(sp[0] + bd0.x, 0.f), v1 = fmaxf(sp[1] + bd0.y, 0.f);
                float v2 = fmaxf(sp[2] + bd0.z, 0.f), v3 = fmaxf(sp[3] + bd0.w, 0.f);
                float v4 = fmaxf(sp[4] + bd1.x, 0.f), v5 = fmaxf(sp[5] + bd1.y, 0.f);
                float v6 = fmaxf(sp[6] + bd1.z, 0.f), v7 = fmaxf(sp[7] + bd1.w, 0.f);
                *(uint4*)(g_x1h + (size_t)gr * NHID + gc) =
                    make_uint4(h2u(__floats2half2_rn(v0, v1)), h2u(__floats2half2_rn(v2, v3)),
                               h2u(__floats2half2_rn(v4, v5)), h2u(__floats2half2_rn(v6, v7)));
                __syncwarp();
            }
        __syncthreads();
    }
}

// =========================================================================
// out gemm (fp16 HMMA, cp.async double-buffered): g_support2h = [x1;h1] @ W2
// M=NP, K=512, N=64 (pre-padded). fp16 output via smem staging.
// =========================================================================
__global__ __launch_bounds__(256) void out_tc() {
    __shared__ __half As[2][128][40];
    __shared__ __half Bs[2][32][72];
    const int t   = threadIdx.x;
    const int wid = t >> 5;
    const int wr  = wid >> 1;     // 0..3
    const int wc  = wid & 1;      // 0..1
    const int row0 = blockIdx.x * 128;

    wmma::fragment<wmma::accumulator, 16, 16, 16, float> acc[2][2];
#pragma unroll
    for (int i = 0; i < 2; i++)
#pragma unroll
        for (int j = 0; j < 2; j++) wmma::fill_fragment(acc[i][j], 0.0f);

    const int arow = t >> 1;
    const int ac16 = (t & 1) * 16;
    const int brow = t >> 3;          // 0..31
    const int bc8  = (t & 7) * 8;     // 0..56
    int garow = row0 + arow; if (garow >= NN) garow = NN - 1;
    const __half* Ap1 = g_x1h + (size_t)garow * NHID;
    const __half* Ap2 = g_h1h + (size_t)garow * NHID;

    const int NIT = 2 * NHID / 32;   // 16
    {
        const __half* ap = Ap1 + ac16;
        cp_async16(&As[0][arow][ac16],     ap);
        cp_async16(&As[0][arow][ac16 + 8], ap + 8);
        cp_async16(&Bs[0][brow][bc8], g_w2h + (size_t)brow * 64 + bc8);
    }
    cp_commit();

    for (int i = 0; i < NIT; i++) {
        if (i + 1 < NIT) {
            int k1 = (i + 1) * 32;
            int nb = (i + 1) & 1;
            const __half* ap = (k1 < NHID) ? (Ap1 + k1 + ac16)
                                           : (Ap2 + (k1 - NHID) + ac16);
            cp_async16(&As[nb][arow][ac16],     ap);
            cp_async16(&As[nb][arow][ac16 + 8], ap + 8);
            cp_async16(&Bs[nb][brow][bc8], g_w2h + (size_t)(k1 + brow) * 64 + bc8);
            cp_commit();
            cp_wait1();
        } else {
            cp_wait0();
        }
        __syncthreads();
        int cb = i & 1;
#pragma unroll
        for (int kk = 0; kk < 32; kk += 16) {
            wmma::fragment<wmma::matrix_a, 16, 16, 16, __half, wmma::row_major> af[2];
            wmma::fragment<wmma::matrix_b, 16, 16, 16, __half, wmma::row_major> bf[2];
#pragma unroll
            for (int ii = 0; ii < 2; ii++)
                wmma::load_matrix_sync(af[ii], &As[cb][wr * 32 + ii * 16][kk], 40);
#pragma unroll
            for (int j = 0; j < 2; j++)
                wmma::load_matrix_sync(bf[j], &Bs[cb][kk][wc * 32 + j * 16], 72);
#pragma unroll
            for (int ii = 0; ii < 2; ii++)
#pragma unroll
                for (int j = 0; j < 2; j++)
                    wmma::mma_sync(acc[ii][j], af[ii], bf[j], acc[ii][j]);
        }
        __syncthreads();
    }

    // fp16 epilogue via staging (reuse As)
    float* stage = (float*)&As[0][0][0] + wid * 320;
    const int L = t & 31;
    const int rr = L >> 1;
    const int cc = (L & 1) * 8;
#pragma unroll
    for (int i = 0; i < 2; i++)
#pragma unroll
        for (int j = 0; j < 2; j++) {
            wmma::store_matrix_sync(stage, acc[i][j], 20, wmma::mem_row_major);
            __syncwarp();
            const float* sp = stage + rr * 20 + cc;
            int r = row0 + wr * 32 + i * 16 + rr;
            int c = wc * 32 + j * 16 + cc;
            *(uint4*)(g_support2h + (size_t)r * 64 + c) =
                make_uint4(h2u(__floats2half2_rn(sp[0], sp[1])),
                           h2u(__floats2half2_rn(sp[2], sp[3])),
                           h2u(__floats2half2_rn(sp[4], sp[5])),
                           h2u(__floats2half2_rn(sp[6], sp[7])));
            __syncwarp();
        }
}

// ---------------- spmm1 + bias + relu (fp16 gather -> fp16 h1) -----------
__global__ void spmm_relu_kernel(const float* __restrict__ b1) {
    int warp = (blockIdx.x * blockDim.x + threadIdx.x) >> 5;
    int lane = threadIdx.x & 31;
    if (warp >= NN) return;
    int beg = g_rowptr[warp];
    int end = g_rowptr[warp + 1];
    float acc[8] = {0, 0, 0, 0, 0, 0, 0, 0};
    const int co = lane * 8;
    int e = beg;
    for (; e + 4 <= end; e += 4) {
        int   s0 = g_esrc[e],   s1 = g_esrc[e + 1], s2 = g_esrc[e + 2], s3 = g_esrc[e + 3];
        float w0 = g_ew[e],     w1 = g_ew[e + 1],   w2 = g_ew[e + 2],   w3 = g_ew[e + 3];
        uint4 u0 = *(const uint4*)(g_support1h + (size_t)s0 * NHID + co);
        uint4 u1 = *(const uint4*)(g_support1h + (size_t)s1 * NHID + co);
        uint4 u2 = *(const uint4*)(g_support1h + (size_t)s2 * NHID + co);
        uint4 u3 = *(const uint4*)(g_support1h + (size_t)s3 * NHID + co);
        __half2* h0 = (__half2*)&u0;
        __half2* h1 = (__half2*)&u1;
        __half2* h2 = (__half2*)&u2;
        __half2* h3 = (__half2*)&u3;
#pragma unroll
        for (int q = 0; q < 4; q++) {
            float2 f0 = __half22float2(h0[q]);
            float2 f1 = __half22float2(h1[q]);
            float2 f2 = __half22float2(h2[q]);
            float2 f3 = __half22float2(h3[q]);
            acc[2 * q]     += w0 * f0.x + w1 * f1.x + w2 * f2.x + w3 * f3.x;
            acc[2 * q + 1] += w0 * f0.y + w1 * f1.y + w2 * f2.y + w3 * f3.y;
        }
    }
    for (; e < end; e++) {
        int s = g_esrc[e];
        float w = g_ew[e];
        uint4 u = *(const uint4*)(g_support1h + (size_t)s * NHID + co);
        __half2* h = (__half2*)&u;
#pragma unroll
        for (int q = 0; q < 4; q++) {
            float2 f = __half22float2(h[q]);
            acc[2 * q]     += w * f.x;
            acc[2 * q + 1] += w * f.y;
        }
    }
    float4 bb0 = *(const float4*)(b1 + co);
    float4 bb1 = *(const float4*)(b1 + co + 4);
    float o[8];
    o[0] = fmaxf(acc[0] + bb0.x, 0.f); o[1] = fmaxf(acc[1] + bb0.y, 0.f);
    o[2] = fmaxf(acc[2] + bb0.z, 0.f); o[3] = fmaxf(acc[3] + bb0.w, 0.f);
    o[4] = fmaxf(acc[4] + bb1.x, 0.f); o[5] = fmaxf(acc[5] + bb1.y, 0.f);
    o[6] = fmaxf(acc[6] + bb1.z, 0.f); o[7] = fmaxf(acc[7] + bb1.w, 0.f);
    uint4 u = make_uint4(h2u(__floats2half2_rn(o[0], o[1])),
                         h2u(__floats2half2_rn(o[2], o[3])),
                         h2u(__floats2half2_rn(o[4], o[5])),
                         h2u(__floats2half2_rn(o[6], o[7])));
    *(uint4*)(g_h1h + (size_t)warp * NHID + co) = u;
}

// ---------------- spmm2 (fp16 gather) + b2 + log_softmax -> out ----------
__global__ void spmm_softmax_kernel(const float* __restrict__ b2,
                                    float* __restrict__ out) {
    int warp = (blockIdx.x * blockDim.x + threadIdx.x) >> 5;
    int lane = threadIdx.x & 31;
    if (warp >= NN) return;
    int beg = g_rowptr[warp];
    int end = g_rowptr[warp + 1];
    bool active = lane < 10;                   // 10 lanes x 4 cols = 40
    float acc[4] = {0, 0, 0, 0};
    for (int e = beg; e < end; e++) {
        int s = g_esrc[e];
        float w = g_ew[e];
        if (active) {
            uint2 u = *(const uint2*)(g_support2h + (size_t)s * 64 + lane * 4);
            __half2* hp = (__half2*)&u;
            float2 f0 = __half22float2(hp[0]);
            float2 f1 = __half22float2(hp[1]);
            acc[0] += w * f0.x; acc[1] += w * f0.y;
            acc[2] += w * f1.x; acc[3] += w * f1.y;
        }
    }
    float4 v = make_float4(-INFINITY, -INFINITY, -INFINITY, -INFINITY);
    if (active) {
        float4 b = *(const float4*)(b2 + lane * 4);
        v.x = acc[0] + b.x; v.y = acc[1] + b.y; v.z = acc[2] + b.z; v.w = acc[3] + b.w;
    }
    float m = fmaxf(fmaxf(v.x, v.y), fmaxf(v.z, v.w));
#pragma unroll
    for (int off = 16; off > 0; off >>= 1)
        m = fmaxf(m, __shfl_xor_sync(0xFFFFFFFFu, m, off));
    float s = active ? (expf(v.x - m) + expf(v.y - m) + expf(v.z - m) + expf(v.w - m)) : 0.0f;
#pragma unroll
    for (int off = 16; off > 0; off >>= 1)
        s += __shfl_xor_sync(0xFFFFFFFFu, s, off);
    float lse = m + logf(s);
    if (active) {
        float4 o;
        o.x = v.x - lse; o.y = v.y - lse; o.z = v.z - lse; o.w = v.w - lse;
        ((float4*)(out + (size_t)warp * NCLASS))[lane] = o;
    }
}

// ---------------- launch ----------------
extern "C" void kernel_launch(void* const* d_in, const int* in_sizes, int n_in,
                              void* d_out, int out_size) {
    const float* x        = (const float*)d_in[0];
    const int*   edge_src = (const int*)  d_in[1];
    const int*   edge_dst = (const int*)  d_in[2];
    const float* edge_w   = (const float*)d_in[3];
    const float* eps      = (const float*)d_in[4];
    const float* W1       = (const float*)d_in[5];
    const float* b1       = (const float*)d_in[6];
    const float* W_mu     = (const float*)d_in[7];
    const float* b_mu     = (const float*)d_in[8];
    const float* W_lv     = (const float*)d_in[9];
    const float* b_lv     = (const float*)d_in[10];
    const float* W_dec    = (const float*)d_in[11];
    const float* b_dec    = (const float*)d_in[12];
    const float* W2       = (const float*)d_in[13];
    const float* b2       = (const float*)d_in[14];
    float* out = (float*)d_out;

    static cudaStream_t s2 = nullptr;
    static cudaEvent_t ev_fork = nullptr, ev_join = nullptr;
    static bool init_done = false;
    if (!init_done) {
        cudaFuncSetAttribute(zdec_tc, cudaFuncAttributeMaxDynamicSharedMemorySize, 65536);
        cudaStreamCreateWithFlags(&s2, cudaStreamNonBlocking);
        cudaEventCreateWithFlags(&ev_fork, cudaEventDisableTiming);
        cudaEventCreateWithFlags(&ev_join, cudaEventDisableTiming);
        init_done = true;
    }

    void* cnt_ptr = nullptr;
    cudaGetSymbolAddress(&cnt_ptr, g_cnt);

    // fork: CSR chain on s2, concurrent with cvt + gemm1 on the main stream
    cudaEventRecord(ev_fork, 0);
    cudaStreamWaitEvent(s2, ev_fork, 0);

    cudaMemsetAsync(cnt_ptr, 0, NN * sizeof(int), s2);
    hist_kernel<<<(EE + 255) / 256, 256, 0, s2>>>(edge_dst);
    scan_kernel<<<1, 1024, 0, s2>>>();
    scatter_kernel<<<(EE + 255) / 256, 256, 0, s2>>>(edge_src, edge_dst, edge_w);
    cudaEventRecord(ev_join, s2);

    cvt_w_kernel<<<(NFEAT * NHID + 255) / 256, 256>>>(W1, W_mu, W_lv, W_dec, W2);
    cvt_x_kernel<<<((size_t)NN * NFEAT / 8 + 255) / 256, 256>>>(x);
    gemm1_tc<<<dim3(NHID / 128, NP / 128), 256>>>();

    // join
    cudaStreamWaitEvent(0, ev_join, 0);

    // h1(fp16) = relu(spmm + b1)
    spmm_relu_kernel<<<(NN * 32 + 255) / 256, 256>>>(b1);

    // fused: tmp -> z -> x1
    zdec_tc<<<NP / 128, 256, 65536>>>(b_mu, b_lv, eps, b_dec);

    // support2(fp16) = [x1; h1] @ W2
    out_tc<<<NP / 128, 256>>>();

    // out = log_softmax(spmm + b2)
    spmm_softmax_kernel<<<(NN * 32 + 255) / 256, 256>>>(b2, out);
}